// round 1
// baseline (speedup 1.0000x reference)
#include <cuda_runtime.h>

#define D_MODEL   1024
#define NUM_HEADS 16
#define HEAD_DIM  64
#define D_FF      4096
#define B_        2
#define S_        2048
#define ROWS      (B_ * S_)   // 4096

// ---------------------------------------------------------------------------
// Scratch (device globals; no allocation allowed)
// ---------------------------------------------------------------------------
__device__ float g_Q   [ROWS * D_MODEL];
__device__ float g_K   [ROWS * D_MODEL];
__device__ float g_V   [ROWS * D_MODEL];
__device__ float g_attn[ROWS * D_MODEL];
__device__ float g_proj[ROWS * D_MODEL];
__device__ float g_x1  [ROWS * D_MODEL];
__device__ float g_ff1 [ROWS * D_FF];
__device__ float g_ff2 [ROWS * D_MODEL];

// ---------------------------------------------------------------------------
// GEMM: C[M,N] = A[M,K] @ B[K,N] + bias[N]  (optional ReLU)
// A row-major, B row-major (K x N). All dims multiples of tile sizes.
// BM=BN=64, BK=16, 256 threads, 4x4 per-thread micro-tile.
// ---------------------------------------------------------------------------
#define BM 64
#define BN 64
#define BK 16

__global__ __launch_bounds__(256)
void gemm_bias_kernel(const float* __restrict__ A,
                      const float* __restrict__ Bm,
                      const float* __restrict__ bias,
                      float* __restrict__ C,
                      int M, int N, int Kd, int relu)
{
    __shared__ float As[BK][BM];
    __shared__ float Bs[BK][BN];

    const int tid = threadIdx.x;
    const int tx  = tid & 15;   // N direction (16)
    const int ty  = tid >> 4;   // M direction (16)
    const int row0 = blockIdx.y * BM;
    const int col0 = blockIdx.x * BN;

    // A tile load mapping: 64 rows x 16 k, one float4 per thread along K
    const int arow = tid >> 2;          // 0..63
    const int acol = (tid & 3) << 2;    // 0,4,8,12
    // B tile load mapping: 16 k-rows x 64 cols, one float4 per thread along N
    const int brow = tid >> 4;          // 0..15
    const int bcol = (tid & 15) << 2;   // 0..60

    const float* Aptr = A  + (size_t)(row0 + arow) * Kd + acol;
    const float* Bptr = Bm + (size_t)brow * N + col0 + bcol;

    float acc[4][4] = {};

    for (int kt = 0; kt < Kd; kt += BK) {
        float4 av = *(const float4*)Aptr;
        Aptr += BK;
        float4 bv = *(const float4*)Bptr;
        Bptr += (size_t)BK * N;

        As[acol + 0][arow] = av.x;
        As[acol + 1][arow] = av.y;
        As[acol + 2][arow] = av.z;
        As[acol + 3][arow] = av.w;
        *(float4*)&Bs[brow][bcol] = bv;

        __syncthreads();

        #pragma unroll
        for (int k = 0; k < BK; k++) {
            float am[4], bn[4];
            #pragma unroll
            for (int i = 0; i < 4; i++) am[i] = As[k][ty * 4 + i];
            #pragma unroll
            for (int j = 0; j < 4; j++) bn[j] = Bs[k][tx * 4 + j];
            #pragma unroll
            for (int i = 0; i < 4; i++)
                #pragma unroll
                for (int j = 0; j < 4; j++)
                    acc[i][j] += am[i] * bn[j];
        }
        __syncthreads();
    }

    const int c0 = col0 + tx * 4;
    float4 bb = *(const float4*)&bias[c0];
    float bv4[4] = {bb.x, bb.y, bb.z, bb.w};

    #pragma unroll
    for (int i = 0; i < 4; i++) {
        const int r = row0 + ty * 4 + i;
        float4 o;
        float v0 = acc[i][0] + bv4[0];
        float v1 = acc[i][1] + bv4[1];
        float v2 = acc[i][2] + bv4[2];
        float v3 = acc[i][3] + bv4[3];
        if (relu) {
            v0 = fmaxf(v0, 0.f); v1 = fmaxf(v1, 0.f);
            v2 = fmaxf(v2, 0.f); v3 = fmaxf(v3, 0.f);
        }
        o.x = v0; o.y = v1; o.z = v2; o.w = v3;
        *(float4*)&C[(size_t)r * N + c0] = o;
    }
}

// ---------------------------------------------------------------------------
// Attention: one thread per query row; K/V tiles of 64 keys staged in smem.
// Online softmax (flash-style). Q/K/V layouts are [B*S, D_MODEL] with head h
// occupying columns [h*64, h*64+64).
// ---------------------------------------------------------------------------
__global__ __launch_bounds__(128)
void attn_kernel(const float* __restrict__ Q,
                 const float* __restrict__ K,
                 const float* __restrict__ V,
                 const int*   __restrict__ mask,
                 float* __restrict__ O)
{
    __shared__ float Ks[64][64];
    __shared__ float Vs[64][64];
    __shared__ int   ms[64];

    const int b = blockIdx.z;
    const int h = blockIdx.y;
    const int q = blockIdx.x * 128 + threadIdx.x;
    const float scale = 0.125f;  // 1/sqrt(64)

    // Load this thread's query row into registers
    float qr[64];
    {
        const float4* qsrc =
            (const float4*)(Q + ((size_t)(b * S_ + q)) * D_MODEL + h * HEAD_DIM);
        #pragma unroll
        for (int i = 0; i < 16; i++) {
            float4 t = qsrc[i];
            qr[4 * i + 0] = t.x; qr[4 * i + 1] = t.y;
            qr[4 * i + 2] = t.z; qr[4 * i + 3] = t.w;
        }
    }

    float o[64];
    #pragma unroll
    for (int d = 0; d < 64; d++) o[d] = 0.f;
    float m = -1e30f, l = 0.f;

    // Tile-load mapping: 128 threads cover 64 keys x 64 dims (2 threads/key)
    const int jr = threadIdx.x >> 1;            // key within tile
    const int dh = (threadIdx.x & 1) * 32;      // dim half

    for (int kt = 0; kt < S_; kt += 64) {
        const float4* ksrc =
            (const float4*)(K + ((size_t)(b * S_ + kt + jr)) * D_MODEL + h * HEAD_DIM + dh);
        const float4* vsrc =
            (const float4*)(V + ((size_t)(b * S_ + kt + jr)) * D_MODEL + h * HEAD_DIM + dh);
        float4* kd = (float4*)&Ks[jr][dh];
        float4* vd = (float4*)&Vs[jr][dh];
        #pragma unroll
        for (int i = 0; i < 8; i++) { kd[i] = ksrc[i]; vd[i] = vsrc[i]; }
        if (threadIdx.x < 64) ms[threadIdx.x] = mask[b * S_ + kt + threadIdx.x];
        __syncthreads();

        for (int j = 0; j < 64; j++) {
            float s = 0.f;
            #pragma unroll
            for (int d = 0; d < 64; d++) s += qr[d] * Ks[j][d];
            s *= scale;
            if (ms[j] == 0) s = -1e9f;

            if (s > m) {
                float corr = __expf(m - s);
                l *= corr;
                #pragma unroll
                for (int d = 0; d < 64; d++) o[d] *= corr;
                m = s;
            }
            float p = __expf(s - m);
            l += p;
            #pragma unroll
            for (int d = 0; d < 64; d++) o[d] += p * Vs[j][d];
        }
        __syncthreads();
    }

    const float inv = 1.f / l;
    float4* dst = (float4*)(O + ((size_t)(b * S_ + q)) * D_MODEL + h * HEAD_DIM);
    #pragma unroll
    for (int i = 0; i < 16; i++) {
        float4 t;
        t.x = o[4 * i + 0] * inv; t.y = o[4 * i + 1] * inv;
        t.z = o[4 * i + 2] * inv; t.w = o[4 * i + 3] * inv;
        dst[i] = t;
    }
}

// ---------------------------------------------------------------------------
// Residual add + LayerNorm: one block per row (1024 elems, 256 threads x f4)
// ---------------------------------------------------------------------------
__global__ __launch_bounds__(256)
void add_ln_kernel(const float* __restrict__ X,
                   const float* __restrict__ Y,
                   const float* __restrict__ g,
                   const float* __restrict__ beta,
                   float* __restrict__ out)
{
    const int row = blockIdx.x;
    const int t = threadIdx.x;
    const float4 a = ((const float4*)(X + (size_t)row * D_MODEL))[t];
    const float4 c = ((const float4*)(Y + (size_t)row * D_MODEL))[t];
    const float v0 = a.x + c.x, v1 = a.y + c.y, v2 = a.z + c.z, v3 = a.w + c.w;

    float s  = v0 + v1 + v2 + v3;
    float ss = v0 * v0 + v1 * v1 + v2 * v2 + v3 * v3;

    #pragma unroll
    for (int off = 16; off; off >>= 1) {
        s  += __shfl_xor_sync(0xffffffffu, s,  off);
        ss += __shfl_xor_sync(0xffffffffu, ss, off);
    }
    __shared__ float ws[8], wss[8];
    const int w = t >> 5;
    if ((t & 31) == 0) { ws[w] = s; wss[w] = ss; }
    __syncthreads();

    float stot = 0.f, sstot = 0.f;
    #pragma unroll
    for (int i = 0; i < 8; i++) { stot += ws[i]; sstot += wss[i]; }

    const float mean = stot * (1.f / 1024.f);
    const float var  = sstot * (1.f / 1024.f) - mean * mean;
    const float r    = rsqrtf(var + 1e-5f);

    const float4 gg = ((const float4*)g)[t];
    const float4 bb = ((const float4*)beta)[t];
    float4 o;
    o.x = (v0 - mean) * r * gg.x + bb.x;
    o.y = (v1 - mean) * r * gg.y + bb.y;
    o.z = (v2 - mean) * r * gg.z + bb.z;
    o.w = (v3 - mean) * r * gg.w + bb.w;
    ((float4*)(out + (size_t)row * D_MODEL))[t] = o;
}

// ---------------------------------------------------------------------------
// Launch
// ---------------------------------------------------------------------------
extern "C" void kernel_launch(void* const* d_in, const int* in_sizes, int n_in,
                              void* d_out, int out_size)
{
    const float* x    = (const float*)d_in[0];
    const int*   mask = (const int*)  d_in[1];
    const float* wq   = (const float*)d_in[2];
    const float* bq   = (const float*)d_in[3];
    const float* wk   = (const float*)d_in[4];
    const float* bk   = (const float*)d_in[5];
    const float* wv   = (const float*)d_in[6];
    const float* bv   = (const float*)d_in[7];
    const float* wo   = (const float*)d_in[8];
    const float* bo   = (const float*)d_in[9];
    const float* w1   = (const float*)d_in[10];
    const float* b1   = (const float*)d_in[11];
    const float* w2   = (const float*)d_in[12];
    const float* b2   = (const float*)d_in[13];
    const float* ln1g = (const float*)d_in[14];
    const float* ln1b = (const float*)d_in[15];
    const float* ln2g = (const float*)d_in[16];
    const float* ln2b = (const float*)d_in[17];

    float *qp, *kp, *vp, *ap, *pp, *x1p, *f1p, *f2p;
    cudaGetSymbolAddress((void**)&qp,  g_Q);
    cudaGetSymbolAddress((void**)&kp,  g_K);
    cudaGetSymbolAddress((void**)&vp,  g_V);
    cudaGetSymbolAddress((void**)&ap,  g_attn);
    cudaGetSymbolAddress((void**)&pp,  g_proj);
    cudaGetSymbolAddress((void**)&x1p, g_x1);
    cudaGetSymbolAddress((void**)&f1p, g_ff1);
    cudaGetSymbolAddress((void**)&f2p, g_ff2);

    const dim3 gProj(D_MODEL / BN, ROWS / BM);   // (16, 64)
    const dim3 gFF1 (D_FF   / BN, ROWS / BM);    // (64, 64)
    const dim3 gFF2 (D_MODEL / BN, ROWS / BM);   // (16, 64)

    // QKV projections
    gemm_bias_kernel<<<gProj, 256>>>(x, wq, bq, qp, ROWS, D_MODEL, D_MODEL, 0);
    gemm_bias_kernel<<<gProj, 256>>>(x, wk, bk, kp, ROWS, D_MODEL, D_MODEL, 0);
    gemm_bias_kernel<<<gProj, 256>>>(x, wv, bv, vp, ROWS, D_MODEL, D_MODEL, 0);

    // Attention
    attn_kernel<<<dim3(S_ / 128, NUM_HEADS, B_), 128>>>(qp, kp, vp, mask, ap);

    // Output projection + residual LN1
    gemm_bias_kernel<<<gProj, 256>>>(ap, wo, bo, pp, ROWS, D_MODEL, D_MODEL, 0);
    add_ln_kernel<<<ROWS, 256>>>(x, pp, ln1g, ln1b, x1p);

    // FFN + residual LN2 -> output
    gemm_bias_kernel<<<gFF1, 256>>>(x1p, w1, b1, f1p, ROWS, D_FF, D_MODEL, 1);
    gemm_bias_kernel<<<gFF2, 256>>>(f1p, w2, b2, f2p, ROWS, D_MODEL, D_FF, 0);
    add_ln_kernel<<<ROWS, 256>>>(x1p, f2p, ln2g, ln2b, (float*)d_out);
}

// round 3
// speedup vs baseline: 1.7710x; 1.7710x over previous
#include <cuda_runtime.h>
#include <cstdint>

#define D_MODEL   1024
#define NUM_HEADS 16
#define HEAD_DIM  64
#define D_FF      4096
#define B_        2
#define S_        2048
#define ROWS      (B_ * S_)   // 4096

// ---------------------------------------------------------------------------
// Scratch (device globals; no allocation allowed)
// ---------------------------------------------------------------------------
__device__ float g_Q   [ROWS * D_MODEL];
__device__ float g_K   [ROWS * D_MODEL];
__device__ float g_V   [ROWS * D_MODEL];
__device__ float g_attn[ROWS * D_MODEL];
__device__ float g_proj[ROWS * D_MODEL];
__device__ float g_x1  [ROWS * D_MODEL];
__device__ float g_ff1 [ROWS * D_FF];
__device__ float g_ff2 [ROWS * D_MODEL];
// Transposed (K-major) weights: Wt[N,K]
__device__ float g_wqt [D_MODEL * D_MODEL];
__device__ float g_wkt [D_MODEL * D_MODEL];
__device__ float g_wvt [D_MODEL * D_MODEL];
__device__ float g_wot [D_MODEL * D_MODEL];
__device__ float g_w1t [D_FF * D_MODEL];
__device__ float g_w2t [D_MODEL * D_FF];

__device__ __forceinline__ uint32_t f2tf32(float x) {
    uint32_t r;
    asm("cvt.rna.tf32.f32 %0, %1;" : "=r"(r) : "f"(x));
    return r;
}

__device__ __forceinline__ void mma_tf32(float* d, const uint32_t* a,
                                         uint32_t b0, uint32_t b1) {
    asm volatile(
        "mma.sync.aligned.m16n8k8.row.col.f32.tf32.tf32.f32 "
        "{%0,%1,%2,%3}, {%4,%5,%6,%7}, {%8,%9}, {%0,%1,%2,%3};"
        : "+f"(d[0]), "+f"(d[1]), "+f"(d[2]), "+f"(d[3])
        : "r"(a[0]), "r"(a[1]), "r"(a[2]), "r"(a[3]), "r"(b0), "r"(b1));
}

// ---------------------------------------------------------------------------
// Weight transpose: W[K,N] row-major -> Wt[N,K] row-major
// ---------------------------------------------------------------------------
__global__ __launch_bounds__(256)
void transpose_kernel(const float* __restrict__ W, float* __restrict__ Wt,
                      int Kd, int N)
{
    __shared__ float t[32][33];
    const int bn = blockIdx.x * 32;
    const int bk = blockIdx.y * 32;
    const int x = threadIdx.x & 31;
    const int y = (threadIdx.x >> 5) * 4;
    #pragma unroll
    for (int i = 0; i < 4; i++)
        t[y + i][x] = W[(size_t)(bk + y + i) * N + bn + x];
    __syncthreads();
    #pragma unroll
    for (int i = 0; i < 4; i++)
        Wt[(size_t)(bn + y + i) * Kd + bk + x] = t[x][y + i];
}

// ---------------------------------------------------------------------------
// Tensor-core (mma.sync tf32) GEMM:
// C[M,N] = A[M,K] @ Bt[N,K]^T + bias[N]   (optional ReLU)
// CTA tile 128x128x32, 8 warps (4 in M x 2 in N), warp tile 32x64.
// SMEM rows padded to 40 floats; float4 columns XOR-swizzled by (row&7).
// ---------------------------------------------------------------------------
#define PAD 40

__global__ __launch_bounds__(256)
void gemm_tc_kernel(const float* __restrict__ A,
                    const float* __restrict__ Bt,
                    const float* __restrict__ bias,
                    float* __restrict__ C,
                    int Kd, int N, int relu)
{
    __shared__ float As[128 * PAD];
    __shared__ float Bs[128 * PAD];

    const int tid  = threadIdx.x;
    const int lane = tid & 31;
    const int wid  = tid >> 5;
    const int g = lane >> 2;   // group id (0..7)
    const int t = lane & 3;    // thread-in-group (0..3)
    const int wm = wid & 3;    // warp M index (0..3)
    const int wn = wid >> 2;   // warp N index (0..1)
    const int row0 = blockIdx.y * 128;
    const int col0 = blockIdx.x * 128;

    float acc[2][8][4];
    #pragma unroll
    for (int mi = 0; mi < 2; mi++)
        #pragma unroll
        for (int ni = 0; ni < 8; ni++)
            #pragma unroll
            for (int j = 0; j < 4; j++) acc[mi][ni][j] = 0.f;

    // Global->SMEM mapping: slot = tid + i*256; r = slot>>3; f4 = slot&7.
    int rr[4], f4l[4], sdst[4];
    const float* aPtr[4];
    const float* bPtr[4];
    #pragma unroll
    for (int i = 0; i < 4; i++) {
        const int slot = tid + i * 256;
        const int r  = slot >> 3;
        const int f4 = slot & 7;
        rr[i] = r; f4l[i] = f4;
        const int f4p = f4 ^ (r & 7);
        sdst[i] = r * PAD + f4p * 4;
        aPtr[i] = A  + (size_t)(row0 + r) * Kd + f4 * 4;
        bPtr[i] = Bt + (size_t)(col0 + r) * Kd + f4 * 4;
    }

    const int NC = Kd >> 5;
    float4 ra[4], rb[4];
    #pragma unroll
    for (int i = 0; i < 4; i++) {
        ra[i] = *(const float4*)(aPtr[i]);
        rb[i] = *(const float4*)(bPtr[i]);
    }

    for (int c = 0; c < NC; c++) {
        __syncthreads();   // previous chunk's compute done
        #pragma unroll
        for (int i = 0; i < 4; i++) {
            uint4 a4, b4;
            a4.x = f2tf32(ra[i].x); a4.y = f2tf32(ra[i].y);
            a4.z = f2tf32(ra[i].z); a4.w = f2tf32(ra[i].w);
            b4.x = f2tf32(rb[i].x); b4.y = f2tf32(rb[i].y);
            b4.z = f2tf32(rb[i].z); b4.w = f2tf32(rb[i].w);
            *(uint4*)&As[sdst[i]] = a4;
            *(uint4*)&Bs[sdst[i]] = b4;
        }
        __syncthreads();

        if (c + 1 < NC) {
            const int ko = (c + 1) * 32;
            #pragma unroll
            for (int i = 0; i < 4; i++) {
                ra[i] = *(const float4*)(aPtr[i] + ko);
                rb[i] = *(const float4*)(bPtr[i] + ko);
            }
        }

        // Compute: 4 k-steps of 8
        #pragma unroll
        for (int ks = 0; ks < 4; ks++) {
            const int c0 = ((2 * ks)     ^ g) * 4 + t;  // phys col, k lo half
            const int c1 = ((2 * ks + 1) ^ g) * 4 + t;  // phys col, k hi half

            uint32_t af[2][4];
            #pragma unroll
            for (int mi = 0; mi < 2; mi++) {
                const int m0 = wm * 32 + mi * 16 + g;
                af[mi][0] = __float_as_uint(As[m0 * PAD + c0]);
                af[mi][1] = __float_as_uint(As[(m0 + 8) * PAD + c0]);
                af[mi][2] = __float_as_uint(As[m0 * PAD + c1]);
                af[mi][3] = __float_as_uint(As[(m0 + 8) * PAD + c1]);
            }
            #pragma unroll
            for (int ni = 0; ni < 8; ni++) {
                const int n0 = wn * 64 + ni * 8 + g;
                const uint32_t b0 = __float_as_uint(Bs[n0 * PAD + c0]);
                const uint32_t b1 = __float_as_uint(Bs[n0 * PAD + c1]);
                mma_tf32(acc[0][ni], af[0], b0, b1);
                mma_tf32(acc[1][ni], af[1], b0, b1);
            }
        }
    }

    // Epilogue: c0/c1 at (row g, col 2t), c2/c3 at (row g+8, col 2t)
    #pragma unroll
    for (int mi = 0; mi < 2; mi++) {
        const int r0 = row0 + wm * 32 + mi * 16 + g;
        #pragma unroll
        for (int ni = 0; ni < 8; ni++) {
            const int col = col0 + wn * 64 + ni * 8 + 2 * t;
            float2 bb = *(const float2*)&bias[col];
            float2 o0, o1;
            o0.x = acc[mi][ni][0] + bb.x;
            o0.y = acc[mi][ni][1] + bb.y;
            o1.x = acc[mi][ni][2] + bb.x;
            o1.y = acc[mi][ni][3] + bb.y;
            if (relu) {
                o0.x = fmaxf(o0.x, 0.f); o0.y = fmaxf(o0.y, 0.f);
                o1.x = fmaxf(o1.x, 0.f); o1.y = fmaxf(o1.y, 0.f);
            }
            *(float2*)&C[(size_t)r0 * N + col]       = o0;
            *(float2*)&C[(size_t)(r0 + 8) * N + col] = o1;
        }
    }
}

// ---------------------------------------------------------------------------
// Attention (fp32 flash-style, one thread per query row)
// ---------------------------------------------------------------------------
__global__ __launch_bounds__(128)
void attn_kernel(const float* __restrict__ Q,
                 const float* __restrict__ K,
                 const float* __restrict__ V,
                 const int*   __restrict__ mask,
                 float* __restrict__ O)
{
    __shared__ float Ks[64][64];
    __shared__ float Vs[64][64];
    __shared__ int   ms[64];

    const int b = blockIdx.z;
    const int h = blockIdx.y;
    const int q = blockIdx.x * 128 + threadIdx.x;
    const float scale = 0.125f;

    float qr[64];
    {
        const float4* qsrc =
            (const float4*)(Q + ((size_t)(b * S_ + q)) * D_MODEL + h * HEAD_DIM);
        #pragma unroll
        for (int i = 0; i < 16; i++) {
            float4 tt = qsrc[i];
            qr[4 * i + 0] = tt.x; qr[4 * i + 1] = tt.y;
            qr[4 * i + 2] = tt.z; qr[4 * i + 3] = tt.w;
        }
    }

    float o[64];
    #pragma unroll
    for (int d = 0; d < 64; d++) o[d] = 0.f;
    float m = -1e30f, l = 0.f;

    const int jr = threadIdx.x >> 1;
    const int dh = (threadIdx.x & 1) * 32;

    for (int kt = 0; kt < S_; kt += 64) {
        const float4* ksrc =
            (const float4*)(K + ((size_t)(b * S_ + kt + jr)) * D_MODEL + h * HEAD_DIM + dh);
        const float4* vsrc =
            (const float4*)(V + ((size_t)(b * S_ + kt + jr)) * D_MODEL + h * HEAD_DIM + dh);
        float4* kd = (float4*)&Ks[jr][dh];
        float4* vd = (float4*)&Vs[jr][dh];
        #pragma unroll
        for (int i = 0; i < 8; i++) { kd[i] = ksrc[i]; vd[i] = vsrc[i]; }
        if (threadIdx.x < 64) ms[threadIdx.x] = mask[b * S_ + kt + threadIdx.x];
        __syncthreads();

        for (int j = 0; j < 64; j++) {
            float s = 0.f;
            #pragma unroll
            for (int d = 0; d < 64; d++) s += qr[d] * Ks[j][d];
            s *= scale;
            if (ms[j] == 0) s = -1e9f;

            if (s > m) {
                float corr = __expf(m - s);
                l *= corr;
                #pragma unroll
                for (int d = 0; d < 64; d++) o[d] *= corr;
                m = s;
            }
            float p = __expf(s - m);
            l += p;
            #pragma unroll
            for (int d = 0; d < 64; d++) o[d] += p * Vs[j][d];
        }
        __syncthreads();
    }

    const float inv = 1.f / l;
    float4* dst = (float4*)(O + ((size_t)(b * S_ + q)) * D_MODEL + h * HEAD_DIM);
    #pragma unroll
    for (int i = 0; i < 16; i++) {
        float4 tt;
        tt.x = o[4 * i + 0] * inv; tt.y = o[4 * i + 1] * inv;
        tt.z = o[4 * i + 2] * inv; tt.w = o[4 * i + 3] * inv;
        dst[i] = tt;
    }
}

// ---------------------------------------------------------------------------
// Residual add + LayerNorm
// ---------------------------------------------------------------------------
__global__ __launch_bounds__(256)
void add_ln_kernel(const float* __restrict__ X,
                   const float* __restrict__ Y,
                   const float* __restrict__ g,
                   const float* __restrict__ beta,
                   float* __restrict__ out)
{
    const int row = blockIdx.x;
    const int t = threadIdx.x;
    const float4 a = ((const float4*)(X + (size_t)row * D_MODEL))[t];
    const float4 c = ((const float4*)(Y + (size_t)row * D_MODEL))[t];
    const float v0 = a.x + c.x, v1 = a.y + c.y, v2 = a.z + c.z, v3 = a.w + c.w;

    float s  = v0 + v1 + v2 + v3;
    float ss = v0 * v0 + v1 * v1 + v2 * v2 + v3 * v3;

    #pragma unroll
    for (int off = 16; off; off >>= 1) {
        s  += __shfl_xor_sync(0xffffffffu, s,  off);
        ss += __shfl_xor_sync(0xffffffffu, ss, off);
    }
    __shared__ float ws[8], wss[8];
    const int w = t >> 5;
    if ((t & 31) == 0) { ws[w] = s; wss[w] = ss; }
    __syncthreads();

    float stot = 0.f, sstot = 0.f;
    #pragma unroll
    for (int i = 0; i < 8; i++) { stot += ws[i]; sstot += wss[i]; }

    const float mean = stot * (1.f / 1024.f);
    const float var  = sstot * (1.f / 1024.f) - mean * mean;
    const float r    = rsqrtf(var + 1e-5f);

    const float4 gg = ((const float4*)g)[t];
    const float4 bb = ((const float4*)beta)[t];
    float4 o;
    o.x = (v0 - mean) * r * gg.x + bb.x;
    o.y = (v1 - mean) * r * gg.y + bb.y;
    o.z = (v2 - mean) * r * gg.z + bb.z;
    o.w = (v3 - mean) * r * gg.w + bb.w;
    ((float4*)(out + (size_t)row * D_MODEL))[t] = o;
}

// ---------------------------------------------------------------------------
// Launch
// ---------------------------------------------------------------------------
extern "C" void kernel_launch(void* const* d_in, const int* in_sizes, int n_in,
                              void* d_out, int out_size)
{
    const float* x    = (const float*)d_in[0];
    const int*   mask = (const int*)  d_in[1];
    const float* wq   = (const float*)d_in[2];
    const float* bq   = (const float*)d_in[3];
    const float* wk   = (const float*)d_in[4];
    const float* bk   = (const float*)d_in[5];
    const float* wv   = (const float*)d_in[6];
    const float* bv   = (const float*)d_in[7];
    const float* wo   = (const float*)d_in[8];
    const float* bo   = (const float*)d_in[9];
    const float* w1   = (const float*)d_in[10];
    const float* b1   = (const float*)d_in[11];
    const float* w2   = (const float*)d_in[12];
    const float* b2   = (const float*)d_in[13];
    const float* ln1g = (const float*)d_in[14];
    const float* ln1b = (const float*)d_in[15];
    const float* ln2g = (const float*)d_in[16];
    const float* ln2b = (const float*)d_in[17];

    float *qp, *kp, *vp, *ap, *pp, *x1p, *f1p, *f2p;
    float *wqt, *wkt, *wvt, *wot, *w1t, *w2t;
    cudaGetSymbolAddress((void**)&qp,  g_Q);
    cudaGetSymbolAddress((void**)&kp,  g_K);
    cudaGetSymbolAddress((void**)&vp,  g_V);
    cudaGetSymbolAddress((void**)&ap,  g_attn);
    cudaGetSymbolAddress((void**)&pp,  g_proj);
    cudaGetSymbolAddress((void**)&x1p, g_x1);
    cudaGetSymbolAddress((void**)&f1p, g_ff1);
    cudaGetSymbolAddress((void**)&f2p, g_ff2);
    cudaGetSymbolAddress((void**)&wqt, g_wqt);
    cudaGetSymbolAddress((void**)&wkt, g_wkt);
    cudaGetSymbolAddress((void**)&wvt, g_wvt);
    cudaGetSymbolAddress((void**)&wot, g_wot);
    cudaGetSymbolAddress((void**)&w1t, g_w1t);
    cudaGetSymbolAddress((void**)&w2t, g_w2t);

    // Transpose weights to K-major [N,K]
    transpose_kernel<<<dim3(D_MODEL / 32, D_MODEL / 32), 256>>>(wq, wqt, D_MODEL, D_MODEL);
    transpose_kernel<<<dim3(D_MODEL / 32, D_MODEL / 32), 256>>>(wk, wkt, D_MODEL, D_MODEL);
    transpose_kernel<<<dim3(D_MODEL / 32, D_MODEL / 32), 256>>>(wv, wvt, D_MODEL, D_MODEL);
    transpose_kernel<<<dim3(D_MODEL / 32, D_MODEL / 32), 256>>>(wo, wot, D_MODEL, D_MODEL);
    transpose_kernel<<<dim3(D_FF / 32,    D_MODEL / 32), 256>>>(w1, w1t, D_MODEL, D_FF);
    transpose_kernel<<<dim3(D_MODEL / 32, D_FF / 32),    256>>>(w2, w2t, D_FF, D_MODEL);

    const dim3 gProj(D_MODEL / 128, ROWS / 128);  // (8, 32)
    const dim3 gFF1 (D_FF   / 128, ROWS / 128);   // (32, 32)
    const dim3 gFF2 (D_MODEL / 128, ROWS / 128);  // (8, 32)

    gemm_tc_kernel<<<gProj, 256>>>(x, wqt, bq, qp, D_MODEL, D_MODEL, 0);
    gemm_tc_kernel<<<gProj, 256>>>(x, wkt, bk, kp, D_MODEL, D_MODEL, 0);
    gemm_tc_kernel<<<gProj, 256>>>(x, wvt, bv, vp, D_MODEL, D_MODEL, 0);

    attn_kernel<<<dim3(S_ / 128, NUM_HEADS, B_), 128>>>(qp, kp, vp, mask, ap);

    gemm_tc_kernel<<<gProj, 256>>>(ap, wot, bo, pp, D_MODEL, D_MODEL, 0);
    add_ln_kernel<<<ROWS, 256>>>(x, pp, ln1g, ln1b, x1p);

    gemm_tc_kernel<<<gFF1, 256>>>(x1p, w1t, b1, f1p, D_MODEL, D_FF, 1);
    gemm_tc_kernel<<<gFF2, 256>>>(f1p, w2t, b2, f2p, D_FF, D_MODEL, 0);
    add_ln_kernel<<<ROWS, 256>>>(x1p, f2p, ln2g, ln2b, (float*)d_out);
}

// round 4
// speedup vs baseline: 3.4731x; 1.9611x over previous
#include <cuda_runtime.h>
#include <cstdint>

#define D_MODEL   1024
#define NUM_HEADS 16
#define HEAD_DIM  64
#define D_FF      4096
#define B_        2
#define S_        2048
#define ROWS      (B_ * S_)   // 4096

// ---------------------------------------------------------------------------
// Scratch (device globals; no allocation allowed)
// ---------------------------------------------------------------------------
__device__ float g_Q   [ROWS * D_MODEL];
__device__ float g_K   [ROWS * D_MODEL];
__device__ float g_V   [ROWS * D_MODEL];
__device__ float g_attn[ROWS * D_MODEL];
__device__ float g_proj[ROWS * D_MODEL];
__device__ float g_x1  [ROWS * D_MODEL];
__device__ float g_ff1 [ROWS * D_FF];
__device__ float g_ff2 [ROWS * D_MODEL];
// Transposed (K-major) weights: Wt[N,K]
__device__ float g_wqt [D_MODEL * D_MODEL];
__device__ float g_wkt [D_MODEL * D_MODEL];
__device__ float g_wvt [D_MODEL * D_MODEL];
__device__ float g_wot [D_MODEL * D_MODEL];
__device__ float g_w1t [D_FF * D_MODEL];
__device__ float g_w2t [D_MODEL * D_FF];

__device__ __forceinline__ uint32_t f2tf32(float x) {
    uint32_t r;
    asm("cvt.rna.tf32.f32 %0, %1;" : "=r"(r) : "f"(x));
    return r;
}
__device__ __forceinline__ float f2tf32f(float x) {
    return __uint_as_float(f2tf32(x));
}

__device__ __forceinline__ void mma_tf32(float* d, const uint32_t* a,
                                         uint32_t b0, uint32_t b1) {
    asm volatile(
        "mma.sync.aligned.m16n8k8.row.col.f32.tf32.tf32.f32 "
        "{%0,%1,%2,%3}, {%4,%5,%6,%7}, {%8,%9}, {%0,%1,%2,%3};"
        : "+f"(d[0]), "+f"(d[1]), "+f"(d[2]), "+f"(d[3])
        : "r"(a[0]), "r"(a[1]), "r"(a[2]), "r"(a[3]), "r"(b0), "r"(b1));
}

// ---------------------------------------------------------------------------
// Weight transpose: W[K,N] row-major -> Wt[N,K] row-major
// ---------------------------------------------------------------------------
__global__ __launch_bounds__(256)
void transpose_kernel(const float* __restrict__ W, float* __restrict__ Wt,
                      int Kd, int N)
{
    __shared__ float t[32][33];
    const int bn = blockIdx.x * 32;
    const int bk = blockIdx.y * 32;
    const int x = threadIdx.x & 31;
    const int y = (threadIdx.x >> 5) * 4;
    #pragma unroll
    for (int i = 0; i < 4; i++)
        t[y + i][x] = W[(size_t)(bk + y + i) * N + bn + x];
    __syncthreads();
    #pragma unroll
    for (int i = 0; i < 4; i++)
        Wt[(size_t)(bn + y + i) * Kd + bk + x] = t[x][y + i];
}

// ---------------------------------------------------------------------------
// Tensor-core (mma.sync tf32) GEMM (unchanged from R3)
// ---------------------------------------------------------------------------
#define PAD 40

__global__ __launch_bounds__(256)
void gemm_tc_kernel(const float* __restrict__ A,
                    const float* __restrict__ Bt,
                    const float* __restrict__ bias,
                    float* __restrict__ C,
                    int Kd, int N, int relu)
{
    __shared__ float As[128 * PAD];
    __shared__ float Bs[128 * PAD];

    const int tid  = threadIdx.x;
    const int lane = tid & 31;
    const int wid  = tid >> 5;
    const int g = lane >> 2;
    const int t = lane & 3;
    const int wm = wid & 3;
    const int wn = wid >> 2;
    const int row0 = blockIdx.y * 128;
    const int col0 = blockIdx.x * 128;

    float acc[2][8][4];
    #pragma unroll
    for (int mi = 0; mi < 2; mi++)
        #pragma unroll
        for (int ni = 0; ni < 8; ni++)
            #pragma unroll
            for (int j = 0; j < 4; j++) acc[mi][ni][j] = 0.f;

    int sdst[4];
    const float* aPtr[4];
    const float* bPtr[4];
    #pragma unroll
    for (int i = 0; i < 4; i++) {
        const int slot = tid + i * 256;
        const int r  = slot >> 3;
        const int f4 = slot & 7;
        const int f4p = f4 ^ (r & 7);
        sdst[i] = r * PAD + f4p * 4;
        aPtr[i] = A  + (size_t)(row0 + r) * Kd + f4 * 4;
        bPtr[i] = Bt + (size_t)(col0 + r) * Kd + f4 * 4;
    }

    const int NC = Kd >> 5;
    float4 ra[4], rb[4];
    #pragma unroll
    for (int i = 0; i < 4; i++) {
        ra[i] = *(const float4*)(aPtr[i]);
        rb[i] = *(const float4*)(bPtr[i]);
    }

    for (int c = 0; c < NC; c++) {
        __syncthreads();
        #pragma unroll
        for (int i = 0; i < 4; i++) {
            uint4 a4, b4;
            a4.x = f2tf32(ra[i].x); a4.y = f2tf32(ra[i].y);
            a4.z = f2tf32(ra[i].z); a4.w = f2tf32(ra[i].w);
            b4.x = f2tf32(rb[i].x); b4.y = f2tf32(rb[i].y);
            b4.z = f2tf32(rb[i].z); b4.w = f2tf32(rb[i].w);
            *(uint4*)&As[sdst[i]] = a4;
            *(uint4*)&Bs[sdst[i]] = b4;
        }
        __syncthreads();

        if (c + 1 < NC) {
            const int ko = (c + 1) * 32;
            #pragma unroll
            for (int i = 0; i < 4; i++) {
                ra[i] = *(const float4*)(aPtr[i] + ko);
                rb[i] = *(const float4*)(bPtr[i] + ko);
            }
        }

        #pragma unroll
        for (int ks = 0; ks < 4; ks++) {
            const int c0 = ((2 * ks)     ^ g) * 4 + t;
            const int c1 = ((2 * ks + 1) ^ g) * 4 + t;

            uint32_t af[2][4];
            #pragma unroll
            for (int mi = 0; mi < 2; mi++) {
                const int m0 = wm * 32 + mi * 16 + g;
                af[mi][0] = __float_as_uint(As[m0 * PAD + c0]);
                af[mi][1] = __float_as_uint(As[(m0 + 8) * PAD + c0]);
                af[mi][2] = __float_as_uint(As[m0 * PAD + c1]);
                af[mi][3] = __float_as_uint(As[(m0 + 8) * PAD + c1]);
            }
            #pragma unroll
            for (int ni = 0; ni < 8; ni++) {
                const int n0 = wn * 64 + ni * 8 + g;
                const uint32_t b0 = __float_as_uint(Bs[n0 * PAD + c0]);
                const uint32_t b1 = __float_as_uint(Bs[n0 * PAD + c1]);
                mma_tf32(acc[0][ni], af[0], b0, b1);
                mma_tf32(acc[1][ni], af[1], b0, b1);
            }
        }
    }

    #pragma unroll
    for (int mi = 0; mi < 2; mi++) {
        const int r0 = row0 + wm * 32 + mi * 16 + g;
        #pragma unroll
        for (int ni = 0; ni < 8; ni++) {
            const int col = col0 + wn * 64 + ni * 8 + 2 * t;
            float2 bb = *(const float2*)&bias[col];
            float2 o0, o1;
            o0.x = acc[mi][ni][0] + bb.x;
            o0.y = acc[mi][ni][1] + bb.y;
            o1.x = acc[mi][ni][2] + bb.x;
            o1.y = acc[mi][ni][3] + bb.y;
            if (relu) {
                o0.x = fmaxf(o0.x, 0.f); o0.y = fmaxf(o0.y, 0.f);
                o1.x = fmaxf(o1.x, 0.f); o1.y = fmaxf(o1.y, 0.f);
            }
            *(float2*)&C[(size_t)r0 * N + col]       = o0;
            *(float2*)&C[(size_t)(r0 + 8) * N + col] = o1;
        }
    }
}

// ---------------------------------------------------------------------------
// Tensor-core flash attention (tf32 mma.sync).
// CTA: 64 query rows for one (b,h). 4 warps; warp w owns rows [w*16, w*16+16).
// Key tiles of 64. SMEM (dynamic, 52480B):
//   Ps [4 warps][16][APAD]  (doubles as Q staging at start)
//   Ks [64][APAD], Vs [64][APAD], ms[64]
// ---------------------------------------------------------------------------
#define APAD 68
#define ATTN_SMEM_FLOATS (3 * 64 * APAD)
#define ATTN_SMEM_BYTES  (ATTN_SMEM_FLOATS * 4 + 64 * 4)

__global__ __launch_bounds__(128)
void attn_tc_kernel(const float* __restrict__ Q,
                    const float* __restrict__ K,
                    const float* __restrict__ V,
                    const int*   __restrict__ mask,
                    float* __restrict__ O)
{
    extern __shared__ float sm[];
    float* Ps = sm;                        // 64*APAD (per-warp slices)
    float* Ks = sm + 64 * APAD;
    float* Vs = sm + 2 * 64 * APAD;
    int*   ms = (int*)(sm + 3 * 64 * APAD);

    const int b  = blockIdx.z;
    const int h  = blockIdx.y;
    const int q0 = blockIdx.x * 64;
    const int tid  = threadIdx.x;
    const int lane = tid & 31;
    const int wid  = tid >> 5;
    const int g = lane >> 2;
    const int t = lane & 3;

    // ---- Stage Q tile (tf32) into Ps, extract per-warp fragments ----
    #pragma unroll
    for (int i = 0; i < 8; i++) {
        const int slot = tid + i * 128;
        const int r = slot >> 4, f4 = slot & 15;
        float4 v = *(const float4*)(Q + (size_t)(b * S_ + q0 + r) * D_MODEL
                                      + h * HEAD_DIM + f4 * 4);
        uint4 u;
        u.x = f2tf32(v.x); u.y = f2tf32(v.y);
        u.z = f2tf32(v.z); u.w = f2tf32(v.w);
        *(uint4*)&Ps[r * APAD + f4 * 4] = u;
    }
    __syncthreads();

    const int mrow = wid * 16 + g;
    uint32_t qf[8][4];
    #pragma unroll
    for (int ks = 0; ks < 8; ks++) {
        qf[ks][0] = __float_as_uint(Ps[mrow * APAD + ks * 8 + t]);
        qf[ks][1] = __float_as_uint(Ps[(mrow + 8) * APAD + ks * 8 + t]);
        qf[ks][2] = __float_as_uint(Ps[mrow * APAD + ks * 8 + t + 4]);
        qf[ks][3] = __float_as_uint(Ps[(mrow + 8) * APAD + ks * 8 + t + 4]);
    }
    __syncthreads();

    float o[8][4];
    #pragma unroll
    for (int ni = 0; ni < 8; ni++)
        #pragma unroll
        for (int j = 0; j < 4; j++) o[ni][j] = 0.f;
    float m0 = -1e30f, m1 = -1e30f, l0 = 0.f, l1 = 0.f;

    float* myP = Ps + wid * 16 * APAD;

    for (int kt = 0; kt < S_; kt += 64) {
        // ---- Load K,V tile (tf32) ----
        #pragma unroll
        for (int i = 0; i < 8; i++) {
            const int slot = tid + i * 128;
            const int r = slot >> 4, f4 = slot & 15;
            const size_t base = (size_t)(b * S_ + kt + r) * D_MODEL + h * HEAD_DIM + f4 * 4;
            float4 kv = *(const float4*)(K + base);
            float4 vv = *(const float4*)(V + base);
            uint4 ku, vu;
            ku.x = f2tf32(kv.x); ku.y = f2tf32(kv.y);
            ku.z = f2tf32(kv.z); ku.w = f2tf32(kv.w);
            vu.x = f2tf32(vv.x); vu.y = f2tf32(vv.y);
            vu.z = f2tf32(vv.z); vu.w = f2tf32(vv.w);
            *(uint4*)&Ks[r * APAD + f4 * 4] = ku;
            *(uint4*)&Vs[r * APAD + f4 * 4] = vu;
        }
        if (tid < 64) ms[tid] = mask[b * S_ + kt + tid];
        __syncthreads();

        // ---- S = Q @ K^T ----
        float s[8][4];
        #pragma unroll
        for (int ni = 0; ni < 8; ni++)
            #pragma unroll
            for (int j = 0; j < 4; j++) s[ni][j] = 0.f;

        #pragma unroll
        for (int ks = 0; ks < 8; ks++) {
            #pragma unroll
            for (int ni = 0; ni < 8; ni++) {
                const int nr = (ni * 8 + g) * APAD + ks * 8 + t;
                const uint32_t b0 = __float_as_uint(Ks[nr]);
                const uint32_t b1 = __float_as_uint(Ks[nr + 4]);
                mma_tf32(s[ni], qf[ks], b0, b1);
            }
        }

        // ---- scale + mask + online softmax ----
        float rmax0 = -1e30f, rmax1 = -1e30f;
        #pragma unroll
        for (int ni = 0; ni < 8; ni++) {
            const int col = ni * 8 + 2 * t;
            const int mz0 = ms[col], mz1 = ms[col + 1];
            float v0 = s[ni][0] * 0.125f; if (mz0 == 0) v0 = -1e9f;
            float v1 = s[ni][1] * 0.125f; if (mz1 == 0) v1 = -1e9f;
            float v2 = s[ni][2] * 0.125f; if (mz0 == 0) v2 = -1e9f;
            float v3 = s[ni][3] * 0.125f; if (mz1 == 0) v3 = -1e9f;
            s[ni][0] = v0; s[ni][1] = v1; s[ni][2] = v2; s[ni][3] = v3;
            rmax0 = fmaxf(rmax0, fmaxf(v0, v1));
            rmax1 = fmaxf(rmax1, fmaxf(v2, v3));
        }
        rmax0 = fmaxf(rmax0, __shfl_xor_sync(0xffffffffu, rmax0, 1));
        rmax0 = fmaxf(rmax0, __shfl_xor_sync(0xffffffffu, rmax0, 2));
        rmax1 = fmaxf(rmax1, __shfl_xor_sync(0xffffffffu, rmax1, 1));
        rmax1 = fmaxf(rmax1, __shfl_xor_sync(0xffffffffu, rmax1, 2));

        const float mn0 = fmaxf(m0, rmax0);
        const float mn1 = fmaxf(m1, rmax1);
        const float c0 = __expf(m0 - mn0);
        const float c1 = __expf(m1 - mn1);

        float rs0 = 0.f, rs1 = 0.f;
        #pragma unroll
        for (int ni = 0; ni < 8; ni++) {
            float p0 = __expf(s[ni][0] - mn0);
            float p1 = __expf(s[ni][1] - mn0);
            float p2 = __expf(s[ni][2] - mn1);
            float p3 = __expf(s[ni][3] - mn1);
            s[ni][0] = p0; s[ni][1] = p1; s[ni][2] = p2; s[ni][3] = p3;
            rs0 += p0 + p1;
            rs1 += p2 + p3;
        }
        rs0 += __shfl_xor_sync(0xffffffffu, rs0, 1);
        rs0 += __shfl_xor_sync(0xffffffffu, rs0, 2);
        rs1 += __shfl_xor_sync(0xffffffffu, rs1, 1);
        rs1 += __shfl_xor_sync(0xffffffffu, rs1, 2);

        l0 = l0 * c0 + rs0;
        l1 = l1 * c1 + rs1;
        #pragma unroll
        for (int ni = 0; ni < 8; ni++) {
            o[ni][0] *= c0; o[ni][1] *= c0;
            o[ni][2] *= c1; o[ni][3] *= c1;
        }
        m0 = mn0; m1 = mn1;

        // ---- P -> per-warp SMEM (tf32), then O += P @ V ----
        #pragma unroll
        for (int ni = 0; ni < 8; ni++) {
            const int col = ni * 8 + 2 * t;
            myP[g * APAD + col]           = f2tf32f(s[ni][0]);
            myP[g * APAD + col + 1]       = f2tf32f(s[ni][1]);
            myP[(g + 8) * APAD + col]     = f2tf32f(s[ni][2]);
            myP[(g + 8) * APAD + col + 1] = f2tf32f(s[ni][3]);
        }
        __syncwarp();

        #pragma unroll
        for (int ks = 0; ks < 8; ks++) {
            uint32_t a[4];
            a[0] = __float_as_uint(myP[g * APAD + ks * 8 + t]);
            a[1] = __float_as_uint(myP[(g + 8) * APAD + ks * 8 + t]);
            a[2] = __float_as_uint(myP[g * APAD + ks * 8 + t + 4]);
            a[3] = __float_as_uint(myP[(g + 8) * APAD + ks * 8 + t + 4]);
            #pragma unroll
            for (int ni = 0; ni < 8; ni++) {
                const uint32_t b0 = __float_as_uint(Vs[(ks * 8 + t) * APAD + ni * 8 + g]);
                const uint32_t b1 = __float_as_uint(Vs[(ks * 8 + t + 4) * APAD + ni * 8 + g]);
                mma_tf32(o[ni], a, b0, b1);
            }
        }
        __syncwarp();
        __syncthreads();   // Ks/Vs reused next iteration
    }

    // ---- Epilogue ----
    const float inv0 = 1.f / l0;
    const float inv1 = 1.f / l1;
    const size_t r0 = (size_t)(b * S_ + q0 + mrow) * D_MODEL + h * HEAD_DIM;
    const size_t r1 = (size_t)(b * S_ + q0 + mrow + 8) * D_MODEL + h * HEAD_DIM;
    #pragma unroll
    for (int ni = 0; ni < 8; ni++) {
        const int col = ni * 8 + 2 * t;
        float2 o0, o1;
        o0.x = o[ni][0] * inv0; o0.y = o[ni][1] * inv0;
        o1.x = o[ni][2] * inv1; o1.y = o[ni][3] * inv1;
        *(float2*)(O + r0 + col) = o0;
        *(float2*)(O + r1 + col) = o1;
    }
}

// ---------------------------------------------------------------------------
// Residual add + LayerNorm
// ---------------------------------------------------------------------------
__global__ __launch_bounds__(256)
void add_ln_kernel(const float* __restrict__ X,
                   const float* __restrict__ Y,
                   const float* __restrict__ g,
                   const float* __restrict__ beta,
                   float* __restrict__ out)
{
    const int row = blockIdx.x;
    const int t = threadIdx.x;
    const float4 a = ((const float4*)(X + (size_t)row * D_MODEL))[t];
    const float4 c = ((const float4*)(Y + (size_t)row * D_MODEL))[t];
    const float v0 = a.x + c.x, v1 = a.y + c.y, v2 = a.z + c.z, v3 = a.w + c.w;

    float s  = v0 + v1 + v2 + v3;
    float ss = v0 * v0 + v1 * v1 + v2 * v2 + v3 * v3;

    #pragma unroll
    for (int off = 16; off; off >>= 1) {
        s  += __shfl_xor_sync(0xffffffffu, s,  off);
        ss += __shfl_xor_sync(0xffffffffu, ss, off);
    }
    __shared__ float ws[8], wss[8];
    const int w = t >> 5;
    if ((t & 31) == 0) { ws[w] = s; wss[w] = ss; }
    __syncthreads();

    float stot = 0.f, sstot = 0.f;
    #pragma unroll
    for (int i = 0; i < 8; i++) { stot += ws[i]; sstot += wss[i]; }

    const float mean = stot * (1.f / 1024.f);
    const float var  = sstot * (1.f / 1024.f) - mean * mean;
    const float r    = rsqrtf(var + 1e-5f);

    const float4 gg = ((const float4*)g)[t];
    const float4 bb = ((const float4*)beta)[t];
    float4 o;
    o.x = (v0 - mean) * r * gg.x + bb.x;
    o.y = (v1 - mean) * r * gg.y + bb.y;
    o.z = (v2 - mean) * r * gg.z + bb.z;
    o.w = (v3 - mean) * r * gg.w + bb.w;
    ((float4*)(out + (size_t)row * D_MODEL))[t] = o;
}

// ---------------------------------------------------------------------------
// Launch
// ---------------------------------------------------------------------------
extern "C" void kernel_launch(void* const* d_in, const int* in_sizes, int n_in,
                              void* d_out, int out_size)
{
    const float* x    = (const float*)d_in[0];
    const int*   mask = (const int*)  d_in[1];
    const float* wq   = (const float*)d_in[2];
    const float* bq   = (const float*)d_in[3];
    const float* wk   = (const float*)d_in[4];
    const float* bk   = (const float*)d_in[5];
    const float* wv   = (const float*)d_in[6];
    const float* bv   = (const float*)d_in[7];
    const float* wo   = (const float*)d_in[8];
    const float* bo   = (const float*)d_in[9];
    const float* w1   = (const float*)d_in[10];
    const float* b1   = (const float*)d_in[11];
    const float* w2   = (const float*)d_in[12];
    const float* b2   = (const float*)d_in[13];
    const float* ln1g = (const float*)d_in[14];
    const float* ln1b = (const float*)d_in[15];
    const float* ln2g = (const float*)d_in[16];
    const float* ln2b = (const float*)d_in[17];

    float *qp, *kp, *vp, *ap, *pp, *x1p, *f1p, *f2p;
    float *wqt, *wkt, *wvt, *wot, *w1t, *w2t;
    cudaGetSymbolAddress((void**)&qp,  g_Q);
    cudaGetSymbolAddress((void**)&kp,  g_K);
    cudaGetSymbolAddress((void**)&vp,  g_V);
    cudaGetSymbolAddress((void**)&ap,  g_attn);
    cudaGetSymbolAddress((void**)&pp,  g_proj);
    cudaGetSymbolAddress((void**)&x1p, g_x1);
    cudaGetSymbolAddress((void**)&f1p, g_ff1);
    cudaGetSymbolAddress((void**)&f2p, g_ff2);
    cudaGetSymbolAddress((void**)&wqt, g_wqt);
    cudaGetSymbolAddress((void**)&wkt, g_wkt);
    cudaGetSymbolAddress((void**)&wvt, g_wvt);
    cudaGetSymbolAddress((void**)&wot, g_wot);
    cudaGetSymbolAddress((void**)&w1t, g_w1t);
    cudaGetSymbolAddress((void**)&w2t, g_w2t);

    static int smem_set = 0;
    if (!smem_set) {
        cudaFuncSetAttribute(attn_tc_kernel,
                             cudaFuncAttributeMaxDynamicSharedMemorySize,
                             ATTN_SMEM_BYTES);
        smem_set = 1;
    }

    // Transpose weights to K-major [N,K]
    transpose_kernel<<<dim3(D_MODEL / 32, D_MODEL / 32), 256>>>(wq, wqt, D_MODEL, D_MODEL);
    transpose_kernel<<<dim3(D_MODEL / 32, D_MODEL / 32), 256>>>(wk, wkt, D_MODEL, D_MODEL);
    transpose_kernel<<<dim3(D_MODEL / 32, D_MODEL / 32), 256>>>(wv, wvt, D_MODEL, D_MODEL);
    transpose_kernel<<<dim3(D_MODEL / 32, D_MODEL / 32), 256>>>(wo, wot, D_MODEL, D_MODEL);
    transpose_kernel<<<dim3(D_FF / 32,    D_MODEL / 32), 256>>>(w1, w1t, D_MODEL, D_FF);
    transpose_kernel<<<dim3(D_MODEL / 32, D_FF / 32),    256>>>(w2, w2t, D_FF, D_MODEL);

    const dim3 gProj(D_MODEL / 128, ROWS / 128);  // (8, 32)
    const dim3 gFF1 (D_FF   / 128, ROWS / 128);   // (32, 32)
    const dim3 gFF2 (D_MODEL / 128, ROWS / 128);  // (8, 32)

    gemm_tc_kernel<<<gProj, 256>>>(x, wqt, bq, qp, D_MODEL, D_MODEL, 0);
    gemm_tc_kernel<<<gProj, 256>>>(x, wkt, bk, kp, D_MODEL, D_MODEL, 0);
    gemm_tc_kernel<<<gProj, 256>>>(x, wvt, bv, vp, D_MODEL, D_MODEL, 0);

    attn_tc_kernel<<<dim3(S_ / 64, NUM_HEADS, B_), 128, ATTN_SMEM_BYTES>>>(
        qp, kp, vp, mask, ap);

    gemm_tc_kernel<<<gProj, 256>>>(ap, wot, bo, pp, D_MODEL, D_MODEL, 0);
    add_ln_kernel<<<ROWS, 256>>>(x, pp, ln1g, ln1b, x1p);

    gemm_tc_kernel<<<gFF1, 256>>>(x1p, w1t, b1, f1p, D_MODEL, D_FF, 1);
    gemm_tc_kernel<<<gFF2, 256>>>(f1p, w2t, b2, f2p, D_FF, D_MODEL, 0);
    add_ln_kernel<<<ROWS, 256>>>(x1p, f2p, ln2g, ln2b, (float*)d_out);
}

// round 5
// speedup vs baseline: 3.9805x; 1.1461x over previous
#include <cuda_runtime.h>
#include <cstdint>

#define D_MODEL   1024
#define NUM_HEADS 16
#define HEAD_DIM  64
#define D_FF      4096
#define B_        2
#define S_        2048
#define ROWS      (B_ * S_)   // 4096
#define QKV_N     (3 * D_MODEL)

// ---------------------------------------------------------------------------
// Scratch (device globals; no allocation allowed)
// ---------------------------------------------------------------------------
__device__ float g_xt  [ROWS * D_MODEL];      // tf32-rounded input
__device__ float g_qkv [ROWS * QKV_N];        // fused QKV output
__device__ float g_attn[ROWS * D_MODEL];      // attention out (tf32-rounded)
__device__ float g_proj[ROWS * D_MODEL];
__device__ float g_x1  [ROWS * D_MODEL];      // ln1 out fp32
__device__ float g_x1t [ROWS * D_MODEL];      // ln1 out tf32-rounded
__device__ float g_ff1 [ROWS * D_FF];         // relu out (tf32-rounded)
__device__ float g_ff2 [ROWS * D_MODEL];
// Transposed + tf32-rounded weights (K-major [N,K])
__device__ float g_wqkvt[QKV_N * D_MODEL];
__device__ float g_wot  [D_MODEL * D_MODEL];
__device__ float g_w1t  [D_FF * D_MODEL];
__device__ float g_w2t  [D_MODEL * D_FF];
__device__ float g_bqkv [QKV_N];

__device__ __forceinline__ uint32_t f2tf32(float x) {
    uint32_t r;
    asm("cvt.rna.tf32.f32 %0, %1;" : "=r"(r) : "f"(x));
    return r;
}
__device__ __forceinline__ float f2tf32f(float x) {
    return __uint_as_float(f2tf32(x));
}
__device__ __forceinline__ uint32_t smem_u32(const void* p) {
    uint32_t a;
    asm("{ .reg .u64 t; cvta.to.shared.u64 t, %1; cvt.u32.u64 %0, t; }"
        : "=r"(a) : "l"(p));
    return a;
}
__device__ __forceinline__ void mma_tf32(float* d, const uint32_t* a,
                                         uint32_t b0, uint32_t b1) {
    asm volatile(
        "mma.sync.aligned.m16n8k8.row.col.f32.tf32.tf32.f32 "
        "{%0,%1,%2,%3}, {%4,%5,%6,%7}, {%8,%9}, {%0,%1,%2,%3};"
        : "+f"(d[0]), "+f"(d[1]), "+f"(d[2]), "+f"(d[3])
        : "r"(a[0]), "r"(a[1]), "r"(a[2]), "r"(a[3]), "r"(b0), "r"(b1));
}
#define CP16(dst, src) \
    asm volatile("cp.async.cg.shared.global [%0], [%1], 16;" \
                 :: "r"(dst), "l"(src) : "memory")
#define CP_COMMIT() asm volatile("cp.async.commit_group;" ::: "memory")
#define CP_WAIT1()  asm volatile("cp.async.wait_group 1;" ::: "memory")

// ---------------------------------------------------------------------------
// Weight transpose + tf32 round: W[K,N] -> Wt[N,K]
// ---------------------------------------------------------------------------
__global__ __launch_bounds__(256)
void transpose_kernel(const float* __restrict__ W, float* __restrict__ Wt,
                      int Kd, int N)
{
    __shared__ float t[32][33];
    const int bn = blockIdx.x * 32;
    const int bk = blockIdx.y * 32;
    const int x = threadIdx.x & 31;
    const int y = (threadIdx.x >> 5) * 4;
    #pragma unroll
    for (int i = 0; i < 4; i++)
        t[y + i][x] = W[(size_t)(bk + y + i) * N + bn + x];
    __syncthreads();
    #pragma unroll
    for (int i = 0; i < 4; i++)
        Wt[(size_t)(bn + y + i) * Kd + bk + x] = f2tf32f(t[x][y + i]);
}

// Round-copy: out = tf32(in), n float4s
__global__ __launch_bounds__(256)
void round_copy_kernel(const float* __restrict__ in, float* __restrict__ out)
{
    const int i = blockIdx.x * 256 + threadIdx.x;
    float4 v = ((const float4*)in)[i];
    v.x = f2tf32f(v.x); v.y = f2tf32f(v.y);
    v.z = f2tf32f(v.z); v.w = f2tf32f(v.w);
    ((float4*)out)[i] = v;
}

__global__ __launch_bounds__(256)
void pack_bias_kernel(const float* __restrict__ bq, const float* __restrict__ bk,
                      const float* __restrict__ bv, float* __restrict__ o)
{
    const int i = blockIdx.x * 256 + threadIdx.x;
    float v = (i < 1024) ? bq[i] : (i < 2048) ? bk[i - 1024] : bv[i - 2048];
    o[i] = v;
}

// ---------------------------------------------------------------------------
// cp.async double-buffered tf32 GEMM:
// C[M,N] = A[M,K] @ Bt[N,K]^T + bias[N].  A/Bt pre-rounded to tf32 bits.
// CTA tile 128x128x32, 8 warps, warp tile 32x64.
// Dynamic SMEM: 2 stages x (A 128x40 + B 128x40) floats = 81920 B.
// rr!=0: ReLU + tf32-round the output.
// ---------------------------------------------------------------------------
#define PAD 40
#define STAGE_F 10240          // floats per stage (A+B)
#define GEMM_SMEM_BYTES (2 * STAGE_F * 4)

__global__ __launch_bounds__(256)
void gemm_tc_async(const float* __restrict__ A,
                   const float* __restrict__ Bt,
                   const float* __restrict__ bias,
                   float* __restrict__ C,
                   int Kd, int N, int rr)
{
    extern __shared__ float smg[];
    const uint32_t sbase = smem_u32(smg);

    const int tid  = threadIdx.x;
    const int lane = tid & 31;
    const int wid  = tid >> 5;
    const int g = lane >> 2;
    const int t = lane & 3;
    const int wm = wid & 3;
    const int wn = wid >> 2;
    const int row0 = blockIdx.y * 128;
    const int col0 = blockIdx.x * 128;

    float acc[2][8][4];
    #pragma unroll
    for (int mi = 0; mi < 2; mi++)
        #pragma unroll
        for (int ni = 0; ni < 8; ni++)
            #pragma unroll
            for (int j = 0; j < 4; j++) acc[mi][ni][j] = 0.f;

    uint32_t sdst[4];
    const float* aP[4];
    const float* bP[4];
    #pragma unroll
    for (int i = 0; i < 4; i++) {
        const int slot = tid + i * 256;
        const int r  = slot >> 3;
        const int f4 = slot & 7;
        const int f4p = f4 ^ (r & 7);
        sdst[i] = (uint32_t)(r * PAD + f4p * 4) * 4u;   // bytes
        aP[i] = A  + (size_t)(row0 + r) * Kd + f4 * 4;
        bP[i] = Bt + (size_t)(col0 + r) * Kd + f4 * 4;
    }

    const int NC = Kd >> 5;

    // Preload chunk 0 into stage 0
    #pragma unroll
    for (int i = 0; i < 4; i++) {
        CP16(sbase + sdst[i], aP[i]);
        CP16(sbase + 20480u + sdst[i], bP[i]);
    }
    CP_COMMIT();

    for (int c = 0; c < NC; c++) {
        if (c + 1 < NC) {
            const int ko = (c + 1) * 32;
            const uint32_t st = (uint32_t)((c + 1) & 1) * 40960u;
            #pragma unroll
            for (int i = 0; i < 4; i++) {
                CP16(sbase + st + sdst[i], aP[i] + ko);
                CP16(sbase + st + 20480u + sdst[i], bP[i] + ko);
            }
        }
        CP_COMMIT();
        CP_WAIT1();
        __syncthreads();

        const float* As = smg + (c & 1) * STAGE_F;
        const float* Bs = As + 5120;

        #pragma unroll
        for (int ks = 0; ks < 4; ks++) {
            const int c0 = ((2 * ks)     ^ g) * 4 + t;
            const int c1 = ((2 * ks + 1) ^ g) * 4 + t;

            uint32_t af[2][4];
            #pragma unroll
            for (int mi = 0; mi < 2; mi++) {
                const int m0 = wm * 32 + mi * 16 + g;
                af[mi][0] = __float_as_uint(As[m0 * PAD + c0]);
                af[mi][1] = __float_as_uint(As[(m0 + 8) * PAD + c0]);
                af[mi][2] = __float_as_uint(As[m0 * PAD + c1]);
                af[mi][3] = __float_as_uint(As[(m0 + 8) * PAD + c1]);
            }
            #pragma unroll
            for (int ni = 0; ni < 8; ni++) {
                const int n0 = wn * 64 + ni * 8 + g;
                const uint32_t b0 = __float_as_uint(Bs[n0 * PAD + c0]);
                const uint32_t b1 = __float_as_uint(Bs[n0 * PAD + c1]);
                mma_tf32(acc[0][ni], af[0], b0, b1);
                mma_tf32(acc[1][ni], af[1], b0, b1);
            }
        }
        __syncthreads();
    }

    #pragma unroll
    for (int mi = 0; mi < 2; mi++) {
        const int r0 = row0 + wm * 32 + mi * 16 + g;
        #pragma unroll
        for (int ni = 0; ni < 8; ni++) {
            const int col = col0 + wn * 64 + ni * 8 + 2 * t;
            float2 bb = *(const float2*)&bias[col];
            float2 o0, o1;
            o0.x = acc[mi][ni][0] + bb.x;
            o0.y = acc[mi][ni][1] + bb.y;
            o1.x = acc[mi][ni][2] + bb.x;
            o1.y = acc[mi][ni][3] + bb.y;
            if (rr) {
                o0.x = f2tf32f(fmaxf(o0.x, 0.f)); o0.y = f2tf32f(fmaxf(o0.y, 0.f));
                o1.x = f2tf32f(fmaxf(o1.x, 0.f)); o1.y = f2tf32f(fmaxf(o1.y, 0.f));
            }
            *(float2*)&C[(size_t)r0 * N + col]       = o0;
            *(float2*)&C[(size_t)(r0 + 8) * N + col] = o1;
        }
    }
}

// ---------------------------------------------------------------------------
// Tensor-core flash attention (tf32 mma.sync), reading packed QKV [ROWS, 3072].
// Output tf32-rounded (consumed only by O-proj GEMM).
// ---------------------------------------------------------------------------
#define APAD 68
#define ATTN_SMEM_BYTES (3 * 64 * APAD * 4 + 64 * 4)

__global__ __launch_bounds__(128)
void attn_tc_kernel(const float* __restrict__ QKV,
                    const int*   __restrict__ mask,
                    float* __restrict__ O)
{
    extern __shared__ float sm[];
    float* Ps = sm;
    float* Ks = sm + 64 * APAD;
    float* Vs = sm + 2 * 64 * APAD;
    int*   ms = (int*)(sm + 3 * 64 * APAD);

    const int b  = blockIdx.z;
    const int h  = blockIdx.y;
    const int q0 = blockIdx.x * 64;
    const int tid  = threadIdx.x;
    const int lane = tid & 31;
    const int wid  = tid >> 5;
    const int g = lane >> 2;
    const int t = lane & 3;

    const int qcol = h * HEAD_DIM;
    const int kcol = D_MODEL + h * HEAD_DIM;
    const int vcol = 2 * D_MODEL + h * HEAD_DIM;

    // ---- Stage Q tile (tf32) into Ps, extract per-warp fragments ----
    #pragma unroll
    for (int i = 0; i < 8; i++) {
        const int slot = tid + i * 128;
        const int r = slot >> 4, f4 = slot & 15;
        float4 v = *(const float4*)(QKV + (size_t)(b * S_ + q0 + r) * QKV_N
                                        + qcol + f4 * 4);
        uint4 u;
        u.x = f2tf32(v.x); u.y = f2tf32(v.y);
        u.z = f2tf32(v.z); u.w = f2tf32(v.w);
        *(uint4*)&Ps[r * APAD + f4 * 4] = u;
    }
    __syncthreads();

    const int mrow = wid * 16 + g;
    uint32_t qf[8][4];
    #pragma unroll
    for (int ks = 0; ks < 8; ks++) {
        qf[ks][0] = __float_as_uint(Ps[mrow * APAD + ks * 8 + t]);
        qf[ks][1] = __float_as_uint(Ps[(mrow + 8) * APAD + ks * 8 + t]);
        qf[ks][2] = __float_as_uint(Ps[mrow * APAD + ks * 8 + t + 4]);
        qf[ks][3] = __float_as_uint(Ps[(mrow + 8) * APAD + ks * 8 + t + 4]);
    }
    __syncthreads();

    float o[8][4];
    #pragma unroll
    for (int ni = 0; ni < 8; ni++)
        #pragma unroll
        for (int j = 0; j < 4; j++) o[ni][j] = 0.f;
    float m0 = -1e30f, m1 = -1e30f, l0 = 0.f, l1 = 0.f;

    float* myP = Ps + wid * 16 * APAD;

    for (int kt = 0; kt < S_; kt += 64) {
        #pragma unroll
        for (int i = 0; i < 8; i++) {
            const int slot = tid + i * 128;
            const int r = slot >> 4, f4 = slot & 15;
            const size_t base = (size_t)(b * S_ + kt + r) * QKV_N + f4 * 4;
            float4 kv = *(const float4*)(QKV + base + kcol);
            float4 vv = *(const float4*)(QKV + base + vcol);
            uint4 ku, vu;
            ku.x = f2tf32(kv.x); ku.y = f2tf32(kv.y);
            ku.z = f2tf32(kv.z); ku.w = f2tf32(kv.w);
            vu.x = f2tf32(vv.x); vu.y = f2tf32(vv.y);
            vu.z = f2tf32(vv.z); vu.w = f2tf32(vv.w);
            *(uint4*)&Ks[r * APAD + f4 * 4] = ku;
            *(uint4*)&Vs[r * APAD + f4 * 4] = vu;
        }
        if (tid < 64) ms[tid] = mask[b * S_ + kt + tid];
        __syncthreads();

        float s[8][4];
        #pragma unroll
        for (int ni = 0; ni < 8; ni++)
            #pragma unroll
            for (int j = 0; j < 4; j++) s[ni][j] = 0.f;

        #pragma unroll
        for (int ks = 0; ks < 8; ks++) {
            #pragma unroll
            for (int ni = 0; ni < 8; ni++) {
                const int nr = (ni * 8 + g) * APAD + ks * 8 + t;
                const uint32_t b0 = __float_as_uint(Ks[nr]);
                const uint32_t b1 = __float_as_uint(Ks[nr + 4]);
                mma_tf32(s[ni], qf[ks], b0, b1);
            }
        }

        float rmax0 = -1e30f, rmax1 = -1e30f;
        #pragma unroll
        for (int ni = 0; ni < 8; ni++) {
            const int col = ni * 8 + 2 * t;
            const int mz0 = ms[col], mz1 = ms[col + 1];
            float v0 = s[ni][0] * 0.125f; if (mz0 == 0) v0 = -1e9f;
            float v1 = s[ni][1] * 0.125f; if (mz1 == 0) v1 = -1e9f;
            float v2 = s[ni][2] * 0.125f; if (mz0 == 0) v2 = -1e9f;
            float v3 = s[ni][3] * 0.125f; if (mz1 == 0) v3 = -1e9f;
            s[ni][0] = v0; s[ni][1] = v1; s[ni][2] = v2; s[ni][3] = v3;
            rmax0 = fmaxf(rmax0, fmaxf(v0, v1));
            rmax1 = fmaxf(rmax1, fmaxf(v2, v3));
        }
        rmax0 = fmaxf(rmax0, __shfl_xor_sync(0xffffffffu, rmax0, 1));
        rmax0 = fmaxf(rmax0, __shfl_xor_sync(0xffffffffu, rmax0, 2));
        rmax1 = fmaxf(rmax1, __shfl_xor_sync(0xffffffffu, rmax1, 1));
        rmax1 = fmaxf(rmax1, __shfl_xor_sync(0xffffffffu, rmax1, 2));

        const float mn0 = fmaxf(m0, rmax0);
        const float mn1 = fmaxf(m1, rmax1);
        const float c0 = __expf(m0 - mn0);
        const float c1 = __expf(m1 - mn1);

        float rs0 = 0.f, rs1 = 0.f;
        #pragma unroll
        for (int ni = 0; ni < 8; ni++) {
            float p0 = __expf(s[ni][0] - mn0);
            float p1 = __expf(s[ni][1] - mn0);
            float p2 = __expf(s[ni][2] - mn1);
            float p3 = __expf(s[ni][3] - mn1);
            s[ni][0] = p0; s[ni][1] = p1; s[ni][2] = p2; s[ni][3] = p3;
            rs0 += p0 + p1;
            rs1 += p2 + p3;
        }
        rs0 += __shfl_xor_sync(0xffffffffu, rs0, 1);
        rs0 += __shfl_xor_sync(0xffffffffu, rs0, 2);
        rs1 += __shfl_xor_sync(0xffffffffu, rs1, 1);
        rs1 += __shfl_xor_sync(0xffffffffu, rs1, 2);

        l0 = l0 * c0 + rs0;
        l1 = l1 * c1 + rs1;
        #pragma unroll
        for (int ni = 0; ni < 8; ni++) {
            o[ni][0] *= c0; o[ni][1] *= c0;
            o[ni][2] *= c1; o[ni][3] *= c1;
        }
        m0 = mn0; m1 = mn1;

        #pragma unroll
        for (int ni = 0; ni < 8; ni++) {
            const int col = ni * 8 + 2 * t;
            myP[g * APAD + col]           = f2tf32f(s[ni][0]);
            myP[g * APAD + col + 1]       = f2tf32f(s[ni][1]);
            myP[(g + 8) * APAD + col]     = f2tf32f(s[ni][2]);
            myP[(g + 8) * APAD + col + 1] = f2tf32f(s[ni][3]);
        }
        __syncwarp();

        #pragma unroll
        for (int ks = 0; ks < 8; ks++) {
            uint32_t a[4];
            a[0] = __float_as_uint(myP[g * APAD + ks * 8 + t]);
            a[1] = __float_as_uint(myP[(g + 8) * APAD + ks * 8 + t]);
            a[2] = __float_as_uint(myP[g * APAD + ks * 8 + t + 4]);
            a[3] = __float_as_uint(myP[(g + 8) * APAD + ks * 8 + t + 4]);
            #pragma unroll
            for (int ni = 0; ni < 8; ni++) {
                const uint32_t b0 = __float_as_uint(Vs[(ks * 8 + t) * APAD + ni * 8 + g]);
                const uint32_t b1 = __float_as_uint(Vs[(ks * 8 + t + 4) * APAD + ni * 8 + g]);
                mma_tf32(o[ni], a, b0, b1);
            }
        }
        __syncwarp();
        __syncthreads();
    }

    const float inv0 = 1.f / l0;
    const float inv1 = 1.f / l1;
    const size_t r0 = (size_t)(b * S_ + q0 + mrow) * D_MODEL + h * HEAD_DIM;
    const size_t r1 = (size_t)(b * S_ + q0 + mrow + 8) * D_MODEL + h * HEAD_DIM;
    #pragma unroll
    for (int ni = 0; ni < 8; ni++) {
        const int col = ni * 8 + 2 * t;
        float2 o0, o1;
        o0.x = f2tf32f(o[ni][0] * inv0); o0.y = f2tf32f(o[ni][1] * inv0);
        o1.x = f2tf32f(o[ni][2] * inv1); o1.y = f2tf32f(o[ni][3] * inv1);
        *(float2*)(O + r0 + col) = o0;
        *(float2*)(O + r1 + col) = o1;
    }
}

// ---------------------------------------------------------------------------
// Residual add + LayerNorm; optional tf32-rounded second output
// ---------------------------------------------------------------------------
__global__ __launch_bounds__(256)
void add_ln_kernel(const float* __restrict__ X,
                   const float* __restrict__ Y,
                   const float* __restrict__ g,
                   const float* __restrict__ beta,
                   float* __restrict__ out,
                   float* __restrict__ outr)
{
    const int row = blockIdx.x;
    const int t = threadIdx.x;
    const float4 a = ((const float4*)(X + (size_t)row * D_MODEL))[t];
    const float4 c = ((const float4*)(Y + (size_t)row * D_MODEL))[t];
    const float v0 = a.x + c.x, v1 = a.y + c.y, v2 = a.z + c.z, v3 = a.w + c.w;

    float s  = v0 + v1 + v2 + v3;
    float ss = v0 * v0 + v1 * v1 + v2 * v2 + v3 * v3;

    #pragma unroll
    for (int off = 16; off; off >>= 1) {
        s  += __shfl_xor_sync(0xffffffffu, s,  off);
        ss += __shfl_xor_sync(0xffffffffu, ss, off);
    }
    __shared__ float ws[8], wss[8];
    const int w = t >> 5;
    if ((t & 31) == 0) { ws[w] = s; wss[w] = ss; }
    __syncthreads();

    float stot = 0.f, sstot = 0.f;
    #pragma unroll
    for (int i = 0; i < 8; i++) { stot += ws[i]; sstot += wss[i]; }

    const float mean = stot * (1.f / 1024.f);
    const float var  = sstot * (1.f / 1024.f) - mean * mean;
    const float r    = rsqrtf(var + 1e-5f);

    const float4 gg = ((const float4*)g)[t];
    const float4 bb = ((const float4*)beta)[t];
    float4 o;
    o.x = (v0 - mean) * r * gg.x + bb.x;
    o.y = (v1 - mean) * r * gg.y + bb.y;
    o.z = (v2 - mean) * r * gg.z + bb.z;
    o.w = (v3 - mean) * r * gg.w + bb.w;
    ((float4*)(out + (size_t)row * D_MODEL))[t] = o;
    if (outr) {
        float4 q;
        q.x = f2tf32f(o.x); q.y = f2tf32f(o.y);
        q.z = f2tf32f(o.z); q.w = f2tf32f(o.w);
        ((float4*)(outr + (size_t)row * D_MODEL))[t] = q;
    }
}

// ---------------------------------------------------------------------------
// Launch
// ---------------------------------------------------------------------------
extern "C" void kernel_launch(void* const* d_in, const int* in_sizes, int n_in,
                              void* d_out, int out_size)
{
    const float* x    = (const float*)d_in[0];
    const int*   mask = (const int*)  d_in[1];
    const float* wq   = (const float*)d_in[2];
    const float* bq   = (const float*)d_in[3];
    const float* wk   = (const float*)d_in[4];
    const float* bk   = (const float*)d_in[5];
    const float* wv   = (const float*)d_in[6];
    const float* bv   = (const float*)d_in[7];
    const float* wo   = (const float*)d_in[8];
    const float* bo   = (const float*)d_in[9];
    const float* w1   = (const float*)d_in[10];
    const float* b1   = (const float*)d_in[11];
    const float* w2   = (const float*)d_in[12];
    const float* b2   = (const float*)d_in[13];
    const float* ln1g = (const float*)d_in[14];
    const float* ln1b = (const float*)d_in[15];
    const float* ln2g = (const float*)d_in[16];
    const float* ln2b = (const float*)d_in[17];

    float *xt, *qkv, *ap, *pp, *x1p, *x1t, *f1p, *f2p;
    float *wqkvt, *wot, *w1t, *w2t, *bqkv;
    cudaGetSymbolAddress((void**)&xt,   g_xt);
    cudaGetSymbolAddress((void**)&qkv,  g_qkv);
    cudaGetSymbolAddress((void**)&ap,   g_attn);
    cudaGetSymbolAddress((void**)&pp,   g_proj);
    cudaGetSymbolAddress((void**)&x1p,  g_x1);
    cudaGetSymbolAddress((void**)&x1t,  g_x1t);
    cudaGetSymbolAddress((void**)&f1p,  g_ff1);
    cudaGetSymbolAddress((void**)&f2p,  g_ff2);
    cudaGetSymbolAddress((void**)&wqkvt, g_wqkvt);
    cudaGetSymbolAddress((void**)&wot,  g_wot);
    cudaGetSymbolAddress((void**)&w1t,  g_w1t);
    cudaGetSymbolAddress((void**)&w2t,  g_w2t);
    cudaGetSymbolAddress((void**)&bqkv, g_bqkv);

    static int attr_set = 0;
    if (!attr_set) {
        cudaFuncSetAttribute(attn_tc_kernel,
                             cudaFuncAttributeMaxDynamicSharedMemorySize,
                             ATTN_SMEM_BYTES);
        cudaFuncSetAttribute(gemm_tc_async,
                             cudaFuncAttributeMaxDynamicSharedMemorySize,
                             GEMM_SMEM_BYTES);
        attr_set = 1;
    }

    // Weight prep (transpose + tf32 round); QKV weights packed into one buffer
    transpose_kernel<<<dim3(D_MODEL / 32, D_MODEL / 32), 256>>>(wq, wqkvt, D_MODEL, D_MODEL);
    transpose_kernel<<<dim3(D_MODEL / 32, D_MODEL / 32), 256>>>(wk, wqkvt + D_MODEL * D_MODEL, D_MODEL, D_MODEL);
    transpose_kernel<<<dim3(D_MODEL / 32, D_MODEL / 32), 256>>>(wv, wqkvt + 2 * D_MODEL * D_MODEL, D_MODEL, D_MODEL);
    transpose_kernel<<<dim3(D_MODEL / 32, D_MODEL / 32), 256>>>(wo, wot, D_MODEL, D_MODEL);
    transpose_kernel<<<dim3(D_FF / 32,    D_MODEL / 32), 256>>>(w1, w1t, D_MODEL, D_FF);
    transpose_kernel<<<dim3(D_MODEL / 32, D_FF / 32),    256>>>(w2, w2t, D_FF, D_MODEL);
    pack_bias_kernel<<<QKV_N / 256, 256>>>(bq, bk, bv, bqkv);
    round_copy_kernel<<<ROWS * D_MODEL / 4 / 256, 256>>>(x, xt);

    // Fused QKV GEMM: [4096,1024] @ [1024,3072] -> [4096,3072]
    gemm_tc_async<<<dim3(QKV_N / 128, ROWS / 128), 256, GEMM_SMEM_BYTES>>>(
        xt, wqkvt, bqkv, qkv, D_MODEL, QKV_N, 0);

    attn_tc_kernel<<<dim3(S_ / 64, NUM_HEADS, B_), 128, ATTN_SMEM_BYTES>>>(
        qkv, mask, ap);

    gemm_tc_async<<<dim3(D_MODEL / 128, ROWS / 128), 256, GEMM_SMEM_BYTES>>>(
        ap, wot, bo, pp, D_MODEL, D_MODEL, 0);
    add_ln_kernel<<<ROWS, 256>>>(x, pp, ln1g, ln1b, x1p, x1t);

    gemm_tc_async<<<dim3(D_FF / 128, ROWS / 128), 256, GEMM_SMEM_BYTES>>>(
        x1t, w1t, b1, f1p, D_MODEL, D_FF, 1);
    gemm_tc_async<<<dim3(D_MODEL / 128, ROWS / 128), 256, GEMM_SMEM_BYTES>>>(
        f1p, w2t, b2, f2p, D_FF, D_MODEL, 0);
    add_ln_kernel<<<ROWS, 256>>>(x1p, f2p, ln2g, ln2b, (float*)d_out, (float*)0);
}

// round 6
// speedup vs baseline: 4.3624x; 1.0959x over previous
#include <cuda_runtime.h>
#include <cstdint>

#define D_MODEL   1024
#define NUM_HEADS 16
#define HEAD_DIM  64
#define D_FF      4096
#define B_        2
#define S_        2048
#define ROWS      (B_ * S_)   // 4096
#define QKV_N     (3 * D_MODEL)

// ---------------------------------------------------------------------------
// Scratch (device globals; no allocation allowed)
// ---------------------------------------------------------------------------
__device__ float g_xt  [ROWS * D_MODEL];      // tf32-rounded input
__device__ float g_qkv [ROWS * QKV_N];        // fused QKV output
__device__ float g_attn[ROWS * D_MODEL];      // attention out (tf32-rounded)
__device__ float g_proj[ROWS * D_MODEL];
__device__ float g_x1  [ROWS * D_MODEL];      // ln1 out fp32
__device__ float g_x1t [ROWS * D_MODEL];      // ln1 out tf32-rounded
__device__ float g_ff1 [ROWS * D_FF];         // relu out (tf32-rounded)
__device__ float g_ff2 [ROWS * D_MODEL];
// Transposed + tf32-rounded weights (K-major [N,K])
__device__ float g_wqkvt[QKV_N * D_MODEL];
__device__ float g_wot  [D_MODEL * D_MODEL];
__device__ float g_w1t  [D_FF * D_MODEL];
__device__ float g_w2t  [D_MODEL * D_FF];
__device__ float g_bqkv [QKV_N];

__device__ __forceinline__ uint32_t f2tf32(float x) {
    uint32_t r;
    asm("cvt.rna.tf32.f32 %0, %1;" : "=r"(r) : "f"(x));
    return r;
}
__device__ __forceinline__ float f2tf32f(float x) {
    return __uint_as_float(f2tf32(x));
}
__device__ __forceinline__ uint32_t smem_u32(const void* p) {
    uint32_t a;
    asm("{ .reg .u64 t; cvta.to.shared.u64 t, %1; cvt.u32.u64 %0, t; }"
        : "=r"(a) : "l"(p));
    return a;
}
__device__ __forceinline__ void mma_tf32(float* d, const uint32_t* a,
                                         uint32_t b0, uint32_t b1) {
    asm volatile(
        "mma.sync.aligned.m16n8k8.row.col.f32.tf32.tf32.f32 "
        "{%0,%1,%2,%3}, {%4,%5,%6,%7}, {%8,%9}, {%0,%1,%2,%3};"
        : "+f"(d[0]), "+f"(d[1]), "+f"(d[2]), "+f"(d[3])
        : "r"(a[0]), "r"(a[1]), "r"(a[2]), "r"(a[3]), "r"(b0), "r"(b1));
}
#define CP16(dst, src) \
    asm volatile("cp.async.cg.shared.global [%0], [%1], 16;" \
                 :: "r"(dst), "l"(src) : "memory")
#define CP_COMMIT() asm volatile("cp.async.commit_group;" ::: "memory")
#define CP_WAIT1()  asm volatile("cp.async.wait_group 1;" ::: "memory")

// ---------------------------------------------------------------------------
// Weight transpose + tf32 round: W[K,N] -> Wt[N,K]
// ---------------------------------------------------------------------------
__global__ __launch_bounds__(256)
void transpose_kernel(const float* __restrict__ W, float* __restrict__ Wt,
                      int Kd, int N)
{
    __shared__ float t[32][33];
    const int bn = blockIdx.x * 32;
    const int bk = blockIdx.y * 32;
    const int x = threadIdx.x & 31;
    const int y = (threadIdx.x >> 5) * 4;
    #pragma unroll
    for (int i = 0; i < 4; i++)
        t[y + i][x] = W[(size_t)(bk + y + i) * N + bn + x];
    __syncthreads();
    #pragma unroll
    for (int i = 0; i < 4; i++)
        Wt[(size_t)(bn + y + i) * Kd + bk + x] = f2tf32f(t[x][y + i]);
}

__global__ __launch_bounds__(256)
void round_copy_kernel(const float* __restrict__ in, float* __restrict__ out)
{
    const int i = blockIdx.x * 256 + threadIdx.x;
    float4 v = ((const float4*)in)[i];
    v.x = f2tf32f(v.x); v.y = f2tf32f(v.y);
    v.z = f2tf32f(v.z); v.w = f2tf32f(v.w);
    ((float4*)out)[i] = v;
}

__global__ __launch_bounds__(256)
void pack_bias_kernel(const float* __restrict__ bq, const float* __restrict__ bk,
                      const float* __restrict__ bv, float* __restrict__ o)
{
    const int i = blockIdx.x * 256 + threadIdx.x;
    float v = (i < 1024) ? bq[i] : (i < 2048) ? bk[i - 1024] : bv[i - 2048];
    o[i] = v;
}

// ---------------------------------------------------------------------------
// cp.async double-buffered tf32 GEMM:
// C[M,N] = A[M,K] @ Bt[N,K]^T + bias[N].  A/Bt pre-rounded to tf32 bits.
// CTA tile 128x128x32, 4 warps (2Mx2N), warp tile 64x64.
// Dynamic SMEM: 2 stages x (A 128x40 + B 128x40) floats = 81920 B.
// rr!=0: ReLU + tf32-round the output.
// ---------------------------------------------------------------------------
#define PAD 40
#define STAGE_F 10240          // floats per stage (A+B)
#define GEMM_SMEM_BYTES (2 * STAGE_F * 4)

__global__ __launch_bounds__(128)
void gemm_tc_async(const float* __restrict__ A,
                   const float* __restrict__ Bt,
                   const float* __restrict__ bias,
                   float* __restrict__ C,
                   int Kd, int N, int rr)
{
    extern __shared__ float smg[];
    const uint32_t sbase = smem_u32(smg);

    const int tid  = threadIdx.x;
    const int lane = tid & 31;
    const int wid  = tid >> 5;
    const int g = lane >> 2;
    const int t = lane & 3;
    const int wm = wid & 1;     // warp M index (0..1), 64 rows each
    const int wn = wid >> 1;    // warp N index (0..1), 64 cols each
    const int row0 = blockIdx.y * 128;
    const int col0 = blockIdx.x * 128;

    float acc[4][8][4];
    #pragma unroll
    for (int mi = 0; mi < 4; mi++)
        #pragma unroll
        for (int ni = 0; ni < 8; ni++)
            #pragma unroll
            for (int j = 0; j < 4; j++) acc[mi][ni][j] = 0.f;

    // cp.async mapping: 8 slots per thread (128 thr * 8 = 1024 f4 per operand)
    uint32_t sdst[8];
    const float* aP[8];
    const float* bP[8];
    #pragma unroll
    for (int i = 0; i < 8; i++) {
        const int slot = tid + i * 128;
        const int r  = slot >> 3;
        const int f4 = slot & 7;
        const int f4p = f4 ^ (r & 7);
        sdst[i] = (uint32_t)(r * PAD + f4p * 4) * 4u;   // bytes
        aP[i] = A  + (size_t)(row0 + r) * Kd + f4 * 4;
        bP[i] = Bt + (size_t)(col0 + r) * Kd + f4 * 4;
    }

    const int NC = Kd >> 5;

    // Preload chunk 0 into stage 0
    #pragma unroll
    for (int i = 0; i < 8; i++) {
        CP16(sbase + sdst[i], aP[i]);
        CP16(sbase + 20480u + sdst[i], bP[i]);
    }
    CP_COMMIT();

    for (int c = 0; c < NC; c++) {
        if (c + 1 < NC) {
            const int ko = (c + 1) * 32;
            const uint32_t st = (uint32_t)((c + 1) & 1) * 40960u;
            #pragma unroll
            for (int i = 0; i < 8; i++) {
                CP16(sbase + st + sdst[i], aP[i] + ko);
                CP16(sbase + st + 20480u + sdst[i], bP[i] + ko);
            }
        }
        CP_COMMIT();
        CP_WAIT1();
        __syncthreads();

        const float* As = smg + (c & 1) * STAGE_F;
        const float* Bs = As + 5120;

        #pragma unroll
        for (int ks = 0; ks < 4; ks++) {
            const int c0 = ((2 * ks)     ^ g) * 4 + t;
            const int c1 = ((2 * ks + 1) ^ g) * 4 + t;

            uint32_t af[4][4];
            #pragma unroll
            for (int mi = 0; mi < 4; mi++) {
                const int m0 = wm * 64 + mi * 16 + g;
                af[mi][0] = __float_as_uint(As[m0 * PAD + c0]);
                af[mi][1] = __float_as_uint(As[(m0 + 8) * PAD + c0]);
                af[mi][2] = __float_as_uint(As[m0 * PAD + c1]);
                af[mi][3] = __float_as_uint(As[(m0 + 8) * PAD + c1]);
            }
            #pragma unroll
            for (int ni = 0; ni < 8; ni++) {
                const int n0 = wn * 64 + ni * 8 + g;
                const uint32_t b0 = __float_as_uint(Bs[n0 * PAD + c0]);
                const uint32_t b1 = __float_as_uint(Bs[n0 * PAD + c1]);
                #pragma unroll
                for (int mi = 0; mi < 4; mi++)
                    mma_tf32(acc[mi][ni], af[mi], b0, b1);
            }
        }
        __syncthreads();
    }

    #pragma unroll
    for (int mi = 0; mi < 4; mi++) {
        const int r0 = row0 + wm * 64 + mi * 16 + g;
        #pragma unroll
        for (int ni = 0; ni < 8; ni++) {
            const int col = col0 + wn * 64 + ni * 8 + 2 * t;
            float2 bb = *(const float2*)&bias[col];
            float2 o0, o1;
            o0.x = acc[mi][ni][0] + bb.x;
            o0.y = acc[mi][ni][1] + bb.y;
            o1.x = acc[mi][ni][2] + bb.x;
            o1.y = acc[mi][ni][3] + bb.y;
            if (rr) {
                o0.x = f2tf32f(fmaxf(o0.x, 0.f)); o0.y = f2tf32f(fmaxf(o0.y, 0.f));
                o1.x = f2tf32f(fmaxf(o1.x, 0.f)); o1.y = f2tf32f(fmaxf(o1.y, 0.f));
            }
            *(float2*)&C[(size_t)r0 * N + col]       = o0;
            *(float2*)&C[(size_t)(r0 + 8) * N + col] = o1;
        }
    }
}

// ---------------------------------------------------------------------------
// Tensor-core flash attention (tf32 mma.sync), reading packed QKV [ROWS, 3072].
// ---------------------------------------------------------------------------
#define APAD 68
#define ATTN_SMEM_BYTES (3 * 64 * APAD * 4 + 64 * 4)

__global__ __launch_bounds__(128)
void attn_tc_kernel(const float* __restrict__ QKV,
                    const int*   __restrict__ mask,
                    float* __restrict__ O)
{
    extern __shared__ float sm[];
    float* Ps = sm;
    float* Ks = sm + 64 * APAD;
    float* Vs = sm + 2 * 64 * APAD;
    int*   ms = (int*)(sm + 3 * 64 * APAD);

    const int b  = blockIdx.z;
    const int h  = blockIdx.y;
    const int q0 = blockIdx.x * 64;
    const int tid  = threadIdx.x;
    const int lane = tid & 31;
    const int wid  = tid >> 5;
    const int g = lane >> 2;
    const int t = lane & 3;

    const int qcol = h * HEAD_DIM;
    const int kcol = D_MODEL + h * HEAD_DIM;
    const int vcol = 2 * D_MODEL + h * HEAD_DIM;

    #pragma unroll
    for (int i = 0; i < 8; i++) {
        const int slot = tid + i * 128;
        const int r = slot >> 4, f4 = slot & 15;
        float4 v = *(const float4*)(QKV + (size_t)(b * S_ + q0 + r) * QKV_N
                                        + qcol + f4 * 4);
        uint4 u;
        u.x = f2tf32(v.x); u.y = f2tf32(v.y);
        u.z = f2tf32(v.z); u.w = f2tf32(v.w);
        *(uint4*)&Ps[r * APAD + f4 * 4] = u;
    }
    __syncthreads();

    const int mrow = wid * 16 + g;
    uint32_t qf[8][4];
    #pragma unroll
    for (int ks = 0; ks < 8; ks++) {
        qf[ks][0] = __float_as_uint(Ps[mrow * APAD + ks * 8 + t]);
        qf[ks][1] = __float_as_uint(Ps[(mrow + 8) * APAD + ks * 8 + t]);
        qf[ks][2] = __float_as_uint(Ps[mrow * APAD + ks * 8 + t + 4]);
        qf[ks][3] = __float_as_uint(Ps[(mrow + 8) * APAD + ks * 8 + t + 4]);
    }
    __syncthreads();

    float o[8][4];
    #pragma unroll
    for (int ni = 0; ni < 8; ni++)
        #pragma unroll
        for (int j = 0; j < 4; j++) o[ni][j] = 0.f;
    float m0 = -1e30f, m1 = -1e30f, l0 = 0.f, l1 = 0.f;

    float* myP = Ps + wid * 16 * APAD;

    for (int kt = 0; kt < S_; kt += 64) {
        #pragma unroll
        for (int i = 0; i < 8; i++) {
            const int slot = tid + i * 128;
            const int r = slot >> 4, f4 = slot & 15;
            const size_t base = (size_t)(b * S_ + kt + r) * QKV_N + f4 * 4;
            float4 kv = *(const float4*)(QKV + base + kcol);
            float4 vv = *(const float4*)(QKV + base + vcol);
            uint4 ku, vu;
            ku.x = f2tf32(kv.x); ku.y = f2tf32(kv.y);
            ku.z = f2tf32(kv.z); ku.w = f2tf32(kv.w);
            vu.x = f2tf32(vv.x); vu.y = f2tf32(vv.y);
            vu.z = f2tf32(vv.z); vu.w = f2tf32(vv.w);
            *(uint4*)&Ks[r * APAD + f4 * 4] = ku;
            *(uint4*)&Vs[r * APAD + f4 * 4] = vu;
        }
        if (tid < 64) ms[tid] = mask[b * S_ + kt + tid];
        __syncthreads();

        float s[8][4];
        #pragma unroll
        for (int ni = 0; ni < 8; ni++)
            #pragma unroll
            for (int j = 0; j < 4; j++) s[ni][j] = 0.f;

        #pragma unroll
        for (int ks = 0; ks < 8; ks++) {
            #pragma unroll
            for (int ni = 0; ni < 8; ni++) {
                const int nr = (ni * 8 + g) * APAD + ks * 8 + t;
                const uint32_t b0 = __float_as_uint(Ks[nr]);
                const uint32_t b1 = __float_as_uint(Ks[nr + 4]);
                mma_tf32(s[ni], qf[ks], b0, b1);
            }
        }

        float rmax0 = -1e30f, rmax1 = -1e30f;
        #pragma unroll
        for (int ni = 0; ni < 8; ni++) {
            const int col = ni * 8 + 2 * t;
            const int mz0 = ms[col], mz1 = ms[col + 1];
            float v0 = s[ni][0] * 0.125f; if (mz0 == 0) v0 = -1e9f;
            float v1 = s[ni][1] * 0.125f; if (mz1 == 0) v1 = -1e9f;
            float v2 = s[ni][2] * 0.125f; if (mz0 == 0) v2 = -1e9f;
            float v3 = s[ni][3] * 0.125f; if (mz1 == 0) v3 = -1e9f;
            s[ni][0] = v0; s[ni][1] = v1; s[ni][2] = v2; s[ni][3] = v3;
            rmax0 = fmaxf(rmax0, fmaxf(v0, v1));
            rmax1 = fmaxf(rmax1, fmaxf(v2, v3));
        }
        rmax0 = fmaxf(rmax0, __shfl_xor_sync(0xffffffffu, rmax0, 1));
        rmax0 = fmaxf(rmax0, __shfl_xor_sync(0xffffffffu, rmax0, 2));
        rmax1 = fmaxf(rmax1, __shfl_xor_sync(0xffffffffu, rmax1, 1));
        rmax1 = fmaxf(rmax1, __shfl_xor_sync(0xffffffffu, rmax1, 2));

        const float mn0 = fmaxf(m0, rmax0);
        const float mn1 = fmaxf(m1, rmax1);
        const float c0 = __expf(m0 - mn0);
        const float c1 = __expf(m1 - mn1);

        float rs0 = 0.f, rs1 = 0.f;
        #pragma unroll
        for (int ni = 0; ni < 8; ni++) {
            float p0 = __expf(s[ni][0] - mn0);
            float p1 = __expf(s[ni][1] - mn0);
            float p2 = __expf(s[ni][2] - mn1);
            float p3 = __expf(s[ni][3] - mn1);
            s[ni][0] = p0; s[ni][1] = p1; s[ni][2] = p2; s[ni][3] = p3;
            rs0 += p0 + p1;
            rs1 += p2 + p3;
        }
        rs0 += __shfl_xor_sync(0xffffffffu, rs0, 1);
        rs0 += __shfl_xor_sync(0xffffffffu, rs0, 2);
        rs1 += __shfl_xor_sync(0xffffffffu, rs1, 1);
        rs1 += __shfl_xor_sync(0xffffffffu, rs1, 2);

        l0 = l0 * c0 + rs0;
        l1 = l1 * c1 + rs1;
        #pragma unroll
        for (int ni = 0; ni < 8; ni++) {
            o[ni][0] *= c0; o[ni][1] *= c0;
            o[ni][2] *= c1; o[ni][3] *= c1;
        }
        m0 = mn0; m1 = mn1;

        #pragma unroll
        for (int ni = 0; ni < 8; ni++) {
            const int col = ni * 8 + 2 * t;
            myP[g * APAD + col]           = f2tf32f(s[ni][0]);
            myP[g * APAD + col + 1]       = f2tf32f(s[ni][1]);
            myP[(g + 8) * APAD + col]     = f2tf32f(s[ni][2]);
            myP[(g + 8) * APAD + col + 1] = f2tf32f(s[ni][3]);
        }
        __syncwarp();

        #pragma unroll
        for (int ks = 0; ks < 8; ks++) {
            uint32_t a[4];
            a[0] = __float_as_uint(myP[g * APAD + ks * 8 + t]);
            a[1] = __float_as_uint(myP[(g + 8) * APAD + ks * 8 + t]);
            a[2] = __float_as_uint(myP[g * APAD + ks * 8 + t + 4]);
            a[3] = __float_as_uint(myP[(g + 8) * APAD + ks * 8 + t + 4]);
            #pragma unroll
            for (int ni = 0; ni < 8; ni++) {
                const uint32_t b0 = __float_as_uint(Vs[(ks * 8 + t) * APAD + ni * 8 + g]);
                const uint32_t b1 = __float_as_uint(Vs[(ks * 8 + t + 4) * APAD + ni * 8 + g]);
                mma_tf32(o[ni], a, b0, b1);
            }
        }
        __syncwarp();
        __syncthreads();
    }

    const float inv0 = 1.f / l0;
    const float inv1 = 1.f / l1;
    const size_t r0 = (size_t)(b * S_ + q0 + mrow) * D_MODEL + h * HEAD_DIM;
    const size_t r1 = (size_t)(b * S_ + q0 + mrow + 8) * D_MODEL + h * HEAD_DIM;
    #pragma unroll
    for (int ni = 0; ni < 8; ni++) {
        const int col = ni * 8 + 2 * t;
        float2 o0, o1;
        o0.x = f2tf32f(o[ni][0] * inv0); o0.y = f2tf32f(o[ni][1] * inv0);
        o1.x = f2tf32f(o[ni][2] * inv1); o1.y = f2tf32f(o[ni][3] * inv1);
        *(float2*)(O + r0 + col) = o0;
        *(float2*)(O + r1 + col) = o1;
    }
}

// ---------------------------------------------------------------------------
// Residual add + LayerNorm; optional tf32-rounded second output
// ---------------------------------------------------------------------------
__global__ __launch_bounds__(256)
void add_ln_kernel(const float* __restrict__ X,
                   const float* __restrict__ Y,
                   const float* __restrict__ g,
                   const float* __restrict__ beta,
                   float* __restrict__ out,
                   float* __restrict__ outr)
{
    const int row = blockIdx.x;
    const int t = threadIdx.x;
    const float4 a = ((const float4*)(X + (size_t)row * D_MODEL))[t];
    const float4 c = ((const float4*)(Y + (size_t)row * D_MODEL))[t];
    const float v0 = a.x + c.x, v1 = a.y + c.y, v2 = a.z + c.z, v3 = a.w + c.w;

    float s  = v0 + v1 + v2 + v3;
    float ss = v0 * v0 + v1 * v1 + v2 * v2 + v3 * v3;

    #pragma unroll
    for (int off = 16; off; off >>= 1) {
        s  += __shfl_xor_sync(0xffffffffu, s,  off);
        ss += __shfl_xor_sync(0xffffffffu, ss, off);
    }
    __shared__ float ws[8], wss[8];
    const int w = t >> 5;
    if ((t & 31) == 0) { ws[w] = s; wss[w] = ss; }
    __syncthreads();

    float stot = 0.f, sstot = 0.f;
    #pragma unroll
    for (int i = 0; i < 8; i++) { stot += ws[i]; sstot += wss[i]; }

    const float mean = stot * (1.f / 1024.f);
    const float var  = sstot * (1.f / 1024.f) - mean * mean;
    const float r    = rsqrtf(var + 1e-5f);

    const float4 gg = ((const float4*)g)[t];
    const float4 bb = ((const float4*)beta)[t];
    float4 o;
    o.x = (v0 - mean) * r * gg.x + bb.x;
    o.y = (v1 - mean) * r * gg.y + bb.y;
    o.z = (v2 - mean) * r * gg.z + bb.z;
    o.w = (v3 - mean) * r * gg.w + bb.w;
    ((float4*)(out + (size_t)row * D_MODEL))[t] = o;
    if (outr) {
        float4 q;
        q.x = f2tf32f(o.x); q.y = f2tf32f(o.y);
        q.z = f2tf32f(o.z); q.w = f2tf32f(o.w);
        ((float4*)(outr + (size_t)row * D_MODEL))[t] = q;
    }
}

// ---------------------------------------------------------------------------
// Launch — ordered so the fused QKV GEMM is launch #6 (ncu -s 5 -c 1 profiles it)
// ---------------------------------------------------------------------------
extern "C" void kernel_launch(void* const* d_in, const int* in_sizes, int n_in,
                              void* d_out, int out_size)
{
    const float* x    = (const float*)d_in[0];
    const int*   mask = (const int*)  d_in[1];
    const float* wq   = (const float*)d_in[2];
    const float* bq   = (const float*)d_in[3];
    const float* wk   = (const float*)d_in[4];
    const float* bk   = (const float*)d_in[5];
    const float* wv   = (const float*)d_in[6];
    const float* bv   = (const float*)d_in[7];
    const float* wo   = (const float*)d_in[8];
    const float* bo   = (const float*)d_in[9];
    const float* w1   = (const float*)d_in[10];
    const float* b1   = (const float*)d_in[11];
    const float* w2   = (const float*)d_in[12];
    const float* b2   = (const float*)d_in[13];
    const float* ln1g = (const float*)d_in[14];
    const float* ln1b = (const float*)d_in[15];
    const float* ln2g = (const float*)d_in[16];
    const float* ln2b = (const float*)d_in[17];

    float *xt, *qkv, *ap, *pp, *x1p, *x1t, *f1p, *f2p;
    float *wqkvt, *wot, *w1t, *w2t, *bqkv;
    cudaGetSymbolAddress((void**)&xt,   g_xt);
    cudaGetSymbolAddress((void**)&qkv,  g_qkv);
    cudaGetSymbolAddress((void**)&ap,   g_attn);
    cudaGetSymbolAddress((void**)&pp,   g_proj);
    cudaGetSymbolAddress((void**)&x1p,  g_x1);
    cudaGetSymbolAddress((void**)&x1t,  g_x1t);
    cudaGetSymbolAddress((void**)&f1p,  g_ff1);
    cudaGetSymbolAddress((void**)&f2p,  g_ff2);
    cudaGetSymbolAddress((void**)&wqkvt, g_wqkvt);
    cudaGetSymbolAddress((void**)&wot,  g_wot);
    cudaGetSymbolAddress((void**)&w1t,  g_w1t);
    cudaGetSymbolAddress((void**)&w2t,  g_w2t);
    cudaGetSymbolAddress((void**)&bqkv, g_bqkv);

    static int attr_set = 0;
    if (!attr_set) {
        cudaFuncSetAttribute(attn_tc_kernel,
                             cudaFuncAttributeMaxDynamicSharedMemorySize,
                             ATTN_SMEM_BYTES);
        cudaFuncSetAttribute(gemm_tc_async,
                             cudaFuncAttributeMaxDynamicSharedMemorySize,
                             GEMM_SMEM_BYTES);
        attr_set = 1;
    }

    // --- Launches 1-5: exactly the QKV GEMM's dependencies ---
    transpose_kernel<<<dim3(D_MODEL / 32, D_MODEL / 32), 256>>>(wq, wqkvt, D_MODEL, D_MODEL);
    transpose_kernel<<<dim3(D_MODEL / 32, D_MODEL / 32), 256>>>(wk, wqkvt + D_MODEL * D_MODEL, D_MODEL, D_MODEL);
    transpose_kernel<<<dim3(D_MODEL / 32, D_MODEL / 32), 256>>>(wv, wqkvt + 2 * D_MODEL * D_MODEL, D_MODEL, D_MODEL);
    pack_bias_kernel<<<QKV_N / 256, 256>>>(bq, bk, bv, bqkv);
    round_copy_kernel<<<ROWS * D_MODEL / 4 / 256, 256>>>(x, xt);

    // --- Launch 6 (profiled): fused QKV GEMM [4096,1024]@[1024,3072] ---
    gemm_tc_async<<<dim3(QKV_N / 128, ROWS / 128), 128, GEMM_SMEM_BYTES>>>(
        xt, wqkvt, bqkv, qkv, D_MODEL, QKV_N, 0);

    // Remaining weight prep (independent of QKV GEMM)
    transpose_kernel<<<dim3(D_MODEL / 32, D_MODEL / 32), 256>>>(wo, wot, D_MODEL, D_MODEL);
    transpose_kernel<<<dim3(D_FF / 32,    D_MODEL / 32), 256>>>(w1, w1t, D_MODEL, D_FF);
    transpose_kernel<<<dim3(D_MODEL / 32, D_FF / 32),    256>>>(w2, w2t, D_FF, D_MODEL);

    attn_tc_kernel<<<dim3(S_ / 64, NUM_HEADS, B_), 128, ATTN_SMEM_BYTES>>>(
        qkv, mask, ap);

    gemm_tc_async<<<dim3(D_MODEL / 128, ROWS / 128), 128, GEMM_SMEM_BYTES>>>(
        ap, wot, bo, pp, D_MODEL, D_MODEL, 0);
    add_ln_kernel<<<ROWS, 256>>>(x, pp, ln1g, ln1b, x1p, x1t);

    gemm_tc_async<<<dim3(D_FF / 128, ROWS / 128), 128, GEMM_SMEM_BYTES>>>(
        x1t, w1t, b1, f1p, D_MODEL, D_FF, 1);
    gemm_tc_async<<<dim3(D_MODEL / 128, ROWS / 128), 128, GEMM_SMEM_BYTES>>>(
        f1p, w2t, b2, f2p, D_FF, D_MODEL, 0);
    add_ln_kernel<<<ROWS, 256>>>(x1p, f2p, ln2g, ln2b, (float*)d_out, (float*)0);
}

// round 8
// speedup vs baseline: 5.6419x; 1.2933x over previous
#include <cuda_runtime.h>
#include <cuda_fp16.h>
#include <cstdint>

#define D_MODEL   1024
#define NUM_HEADS 16
#define HEAD_DIM  64
#define D_FF      4096
#define B_        2
#define S_        2048
#define ROWS      (B_ * S_)   // 4096
#define QKV_N     (3 * D_MODEL)

// ---------------------------------------------------------------------------
// Scratch (device globals; no allocation allowed)
// ---------------------------------------------------------------------------
__device__ __half g_xh  [ROWS * D_MODEL];     // fp16 input
__device__ __half g_qkv [ROWS * QKV_N];       // fused QKV output (fp16)
__device__ __half g_attn[ROWS * D_MODEL];     // attention out (fp16)
__device__ float  g_proj[ROWS * D_MODEL];
__device__ float  g_x1  [ROWS * D_MODEL];     // ln1 out fp32
__device__ __half g_x1h [ROWS * D_MODEL];     // ln1 out fp16
__device__ __half g_ff1 [ROWS * D_FF];        // relu out (fp16)
__device__ float  g_ff2 [ROWS * D_MODEL];
// Transposed fp16 weights (K-major [N,K])
__device__ __half g_wqkvt[QKV_N * D_MODEL];
__device__ __half g_wot  [D_MODEL * D_MODEL];
__device__ __half g_w1t  [D_FF * D_MODEL];
__device__ __half g_w2t  [D_MODEL * D_FF];
__device__ float  g_bqkv [QKV_N];

__device__ __forceinline__ uint32_t smem_u32(const void* p) {
    uint32_t a;
    asm("{ .reg .u64 t; cvta.to.shared.u64 t, %1; cvt.u32.u64 %0, t; }"
        : "=r"(a) : "l"(p));
    return a;
}
__device__ __forceinline__ uint32_t f2tf32(float x) {
    uint32_t r;
    asm("cvt.rna.tf32.f32 %0, %1;" : "=r"(r) : "f"(x));
    return r;
}
__device__ __forceinline__ float f2tf32f(float x) {
    return __uint_as_float(f2tf32(x));
}
// fp16 mma m16n8k16, fp32 accum
__device__ __forceinline__ void mma_f16(float* d, const uint32_t* a,
                                        uint32_t b0, uint32_t b1) {
    asm volatile(
        "mma.sync.aligned.m16n8k16.row.col.f32.f16.f16.f32 "
        "{%0,%1,%2,%3}, {%4,%5,%6,%7}, {%8,%9}, {%0,%1,%2,%3};"
        : "+f"(d[0]), "+f"(d[1]), "+f"(d[2]), "+f"(d[3])
        : "r"(a[0]), "r"(a[1]), "r"(a[2]), "r"(a[3]), "r"(b0), "r"(b1));
}
// tf32 mma m16n8k8, fp32 accum (attention)
__device__ __forceinline__ void mma_tf32(float* d, const uint32_t* a,
                                         uint32_t b0, uint32_t b1) {
    asm volatile(
        "mma.sync.aligned.m16n8k8.row.col.f32.tf32.tf32.f32 "
        "{%0,%1,%2,%3}, {%4,%5,%6,%7}, {%8,%9}, {%0,%1,%2,%3};"
        : "+f"(d[0]), "+f"(d[1]), "+f"(d[2]), "+f"(d[3])
        : "r"(a[0]), "r"(a[1]), "r"(a[2]), "r"(a[3]), "r"(b0), "r"(b1));
}
#define CP16(dst, src) \
    asm volatile("cp.async.cg.shared.global [%0], [%1], 16;" \
                 :: "r"(dst), "l"(src) : "memory")
#define CP_COMMIT() asm volatile("cp.async.commit_group;" ::: "memory")
#define CP_WAIT1()  asm volatile("cp.async.wait_group 1;" ::: "memory")

__device__ __forceinline__ uint32_t pack_h2(float lo, float hi) {
    __half2 h = __floats2half2_rn(lo, hi);
    return *(uint32_t*)&h;
}

// ---------------------------------------------------------------------------
// Fused QKV weight transpose: 3x W[1024,1024] -> half Wt[3072,1024]
// ---------------------------------------------------------------------------
__global__ __launch_bounds__(256)
void transpose3_kernel(const float* __restrict__ wq, const float* __restrict__ wk,
                       const float* __restrict__ wv, __half* __restrict__ out)
{
    __shared__ float t[32][33];
    const float* W = (blockIdx.z == 0) ? wq : (blockIdx.z == 1) ? wk : wv;
    __half* Wt = out + (size_t)blockIdx.z * D_MODEL * D_MODEL;
    const int bn = blockIdx.x * 32;
    const int bk = blockIdx.y * 32;
    const int x = threadIdx.x & 31;
    const int y = (threadIdx.x >> 5) * 4;
    #pragma unroll
    for (int i = 0; i < 4; i++)
        t[y + i][x] = W[(size_t)(bk + y + i) * D_MODEL + bn + x];
    __syncthreads();
    #pragma unroll
    for (int i = 0; i < 4; i++)
        Wt[(size_t)(bn + y + i) * D_MODEL + bk + x] = __float2half(t[x][y + i]);
}

__global__ __launch_bounds__(256)
void transpose_h_kernel(const float* __restrict__ W, __half* __restrict__ Wt,
                        int Kd, int N)
{
    __shared__ float t[32][33];
    const int bn = blockIdx.x * 32;
    const int bk = blockIdx.y * 32;
    const int x = threadIdx.x & 31;
    const int y = (threadIdx.x >> 5) * 4;
    #pragma unroll
    for (int i = 0; i < 4; i++)
        t[y + i][x] = W[(size_t)(bk + y + i) * N + bn + x];
    __syncthreads();
    #pragma unroll
    for (int i = 0; i < 4; i++)
        Wt[(size_t)(bn + y + i) * Kd + bk + x] = __float2half(t[x][y + i]);
}

__global__ __launch_bounds__(256)
void half_copy_kernel(const float* __restrict__ in, __half* __restrict__ out)
{
    const int i = blockIdx.x * 256 + threadIdx.x;   // 8 elems each
    float4 a = ((const float4*)in)[2 * i];
    float4 b = ((const float4*)in)[2 * i + 1];
    uint4 o;
    o.x = pack_h2(a.x, a.y); o.y = pack_h2(a.z, a.w);
    o.z = pack_h2(b.x, b.y); o.w = pack_h2(b.z, b.w);
    ((uint4*)out)[i] = o;
}

__global__ __launch_bounds__(256)
void pack_bias_kernel(const float* __restrict__ bq, const float* __restrict__ bk,
                      const float* __restrict__ bv, float* __restrict__ o)
{
    const int i = blockIdx.x * 256 + threadIdx.x;
    float v = (i < 1024) ? bq[i] : (i < 2048) ? bk[i - 1024] : bv[i - 2048];
    o[i] = v;
}

// ---------------------------------------------------------------------------
// fp16 mma.sync GEMM (unchanged from R7): C = A[M,K] @ Bt[N,K]^T + bias.
// CTA 128x128x32, 4 warps (2Mx2N, warp 64x64), cp.async double-buffered.
// mode: 0 = f32 out; 1 = ReLU + half out; 2 = half out.
// ---------------------------------------------------------------------------
#define GSTR 20
#define GOP  2560

__global__ __launch_bounds__(128)
void gemm_f16(const __half* __restrict__ A,
              const __half* __restrict__ Bt,
              const float* __restrict__ bias,
              void* __restrict__ Cv,
              int Kd, int N, int mode)
{
    __shared__ uint32_t smg[4 * GOP];
    const uint32_t sbase = smem_u32(smg);

    const int tid  = threadIdx.x;
    const int lane = tid & 31;
    const int wid  = tid >> 5;
    const int g = lane >> 2;
    const int t = lane & 3;
    const int wm = wid & 1;
    const int wn = wid >> 1;
    const int row0 = blockIdx.y * 128;
    const int col0 = blockIdx.x * 128;

    float acc[4][8][4];
    #pragma unroll
    for (int mi = 0; mi < 4; mi++)
        #pragma unroll
        for (int ni = 0; ni < 8; ni++)
            #pragma unroll
            for (int j = 0; j < 4; j++) acc[mi][ni][j] = 0.f;

    uint32_t sdst[4];
    const __half* aP[4];
    const __half* bP[4];
    #pragma unroll
    for (int i = 0; i < 4; i++) {
        const int slot = tid + i * 128;
        const int r = slot >> 2, q = slot & 3;
        sdst[i] = (uint32_t)(r * GSTR + q * 4) * 4u;
        aP[i] = A  + (size_t)(row0 + r) * Kd + q * 8;
        bP[i] = Bt + (size_t)(col0 + r) * Kd + q * 8;
    }

    const int NC = Kd >> 5;

    #pragma unroll
    for (int i = 0; i < 4; i++) {
        CP16(sbase + sdst[i], aP[i]);
        CP16(sbase + GOP * 4u + sdst[i], bP[i]);
    }
    CP_COMMIT();

    for (int c = 0; c < NC; c++) {
        if (c + 1 < NC) {
            const int ko = (c + 1) * 32;
            const uint32_t st = (uint32_t)((c + 1) & 1) * (2u * GOP * 4u);
            #pragma unroll
            for (int i = 0; i < 4; i++) {
                CP16(sbase + st + sdst[i], aP[i] + ko);
                CP16(sbase + st + GOP * 4u + sdst[i], bP[i] + ko);
            }
        }
        CP_COMMIT();
        CP_WAIT1();
        __syncthreads();

        const uint32_t* As = smg + (c & 1) * 2 * GOP;
        const uint32_t* Bs = As + GOP;

        #pragma unroll
        for (int ks = 0; ks < 2; ks++) {
            const int kb = ks * 8;
            uint32_t af[4][4];
            #pragma unroll
            for (int mi = 0; mi < 4; mi++) {
                const int m0 = wm * 64 + mi * 16 + g;
                af[mi][0] = As[m0 * GSTR + kb + t];
                af[mi][1] = As[(m0 + 8) * GSTR + kb + t];
                af[mi][2] = As[m0 * GSTR + kb + 4 + t];
                af[mi][3] = As[(m0 + 8) * GSTR + kb + 4 + t];
            }
            #pragma unroll
            for (int ni = 0; ni < 8; ni++) {
                const int n0 = wn * 64 + ni * 8 + g;
                const uint32_t b0 = Bs[n0 * GSTR + kb + t];
                const uint32_t b1 = Bs[n0 * GSTR + kb + 4 + t];
                #pragma unroll
                for (int mi = 0; mi < 4; mi++)
                    mma_f16(acc[mi][ni], af[mi], b0, b1);
            }
        }
        __syncthreads();
    }

    #pragma unroll
    for (int mi = 0; mi < 4; mi++) {
        const int r0 = row0 + wm * 64 + mi * 16 + g;
        #pragma unroll
        for (int ni = 0; ni < 8; ni++) {
            const int col = col0 + wn * 64 + ni * 8 + 2 * t;
            float2 bb = *(const float2*)&bias[col];
            float v00 = acc[mi][ni][0] + bb.x;
            float v01 = acc[mi][ni][1] + bb.y;
            float v10 = acc[mi][ni][2] + bb.x;
            float v11 = acc[mi][ni][3] + bb.y;
            if (mode == 0) {
                float* C = (float*)Cv;
                float2 o0 = {v00, v01}, o1 = {v10, v11};
                *(float2*)&C[(size_t)r0 * N + col]       = o0;
                *(float2*)&C[(size_t)(r0 + 8) * N + col] = o1;
            } else {
                if (mode == 1) {
                    v00 = fmaxf(v00, 0.f); v01 = fmaxf(v01, 0.f);
                    v10 = fmaxf(v10, 0.f); v11 = fmaxf(v11, 0.f);
                }
                __half* C = (__half*)Cv;
                *(uint32_t*)&C[(size_t)r0 * N + col]       = pack_h2(v00, v01);
                *(uint32_t*)&C[(size_t)(r0 + 8) * N + col] = pack_h2(v10, v11);
            }
        }
    }
}

// ---------------------------------------------------------------------------
// tf32 flash attention (R6-proven kernel), fp16 QKV input, fp16 output.
// fp16 -> fp32 is exact; tf32 truncation of fp16 values is exact, so the
// math is identical to R6's.
// ---------------------------------------------------------------------------
#define APAD 68
#define ATTN_SMEM_BYTES (3 * 64 * APAD * 4 + 64 * 4)

__global__ __launch_bounds__(128)
void attn_tc_kernel(const __half* __restrict__ QKV,
                    const int*   __restrict__ mask,
                    __half* __restrict__ O)
{
    extern __shared__ float sm[];
    float* Ps = sm;
    float* Ks = sm + 64 * APAD;
    float* Vs = sm + 2 * 64 * APAD;
    int*   ms = (int*)(sm + 3 * 64 * APAD);

    const int b  = blockIdx.z;
    const int h  = blockIdx.y;
    const int q0 = blockIdx.x * 64;
    const int tid  = threadIdx.x;
    const int lane = tid & 31;
    const int wid  = tid >> 5;
    const int g = lane >> 2;
    const int t = lane & 3;

    const int qc = h * HEAD_DIM;
    const int kc = D_MODEL + h * HEAD_DIM;
    const int vc = 2 * D_MODEL + h * HEAD_DIM;

    // ---- Stage Q tile ----
    #pragma unroll
    for (int i = 0; i < 4; i++) {
        const int slot = tid + i * 128;
        const int r = slot >> 3, h8 = slot & 7;
        uint4 v = *(const uint4*)(QKV + (size_t)(b * S_ + q0 + r) * QKV_N + qc + h8 * 8);
        float2 f0 = __half22float2(*(__half2*)&v.x);
        float2 f1 = __half22float2(*(__half2*)&v.y);
        float2 f2 = __half22float2(*(__half2*)&v.z);
        float2 f3 = __half22float2(*(__half2*)&v.w);
        float4 lo = {f0.x, f0.y, f1.x, f1.y};
        float4 hi = {f2.x, f2.y, f3.x, f3.y};
        *(float4*)&Ps[r * APAD + h8 * 8]     = lo;
        *(float4*)&Ps[r * APAD + h8 * 8 + 4] = hi;
    }
    __syncthreads();

    const int mrow = wid * 16 + g;
    uint32_t qf[8][4];
    #pragma unroll
    for (int ks = 0; ks < 8; ks++) {
        qf[ks][0] = __float_as_uint(Ps[mrow * APAD + ks * 8 + t]);
        qf[ks][1] = __float_as_uint(Ps[(mrow + 8) * APAD + ks * 8 + t]);
        qf[ks][2] = __float_as_uint(Ps[mrow * APAD + ks * 8 + t + 4]);
        qf[ks][3] = __float_as_uint(Ps[(mrow + 8) * APAD + ks * 8 + t + 4]);
    }
    __syncthreads();

    float o[8][4];
    #pragma unroll
    for (int ni = 0; ni < 8; ni++)
        #pragma unroll
        for (int j = 0; j < 4; j++) o[ni][j] = 0.f;
    float m0 = -1e30f, m1 = -1e30f, l0 = 0.f, l1 = 0.f;

    float* myP = Ps + wid * 16 * APAD;

    for (int kt = 0; kt < S_; kt += 64) {
        #pragma unroll
        for (int i = 0; i < 4; i++) {
            const int slot = tid + i * 128;
            const int r = slot >> 3, h8 = slot & 7;
            const size_t base = (size_t)(b * S_ + kt + r) * QKV_N + h8 * 8;
            uint4 kv = *(const uint4*)(QKV + base + kc);
            uint4 vv = *(const uint4*)(QKV + base + vc);
            float2 f0 = __half22float2(*(__half2*)&kv.x);
            float2 f1 = __half22float2(*(__half2*)&kv.y);
            float2 f2 = __half22float2(*(__half2*)&kv.z);
            float2 f3 = __half22float2(*(__half2*)&kv.w);
            float4 klo = {f0.x, f0.y, f1.x, f1.y};
            float4 khi = {f2.x, f2.y, f3.x, f3.y};
            f0 = __half22float2(*(__half2*)&vv.x);
            f1 = __half22float2(*(__half2*)&vv.y);
            f2 = __half22float2(*(__half2*)&vv.z);
            f3 = __half22float2(*(__half2*)&vv.w);
            float4 vlo = {f0.x, f0.y, f1.x, f1.y};
            float4 vhi = {f2.x, f2.y, f3.x, f3.y};
            *(float4*)&Ks[r * APAD + h8 * 8]     = klo;
            *(float4*)&Ks[r * APAD + h8 * 8 + 4] = khi;
            *(float4*)&Vs[r * APAD + h8 * 8]     = vlo;
            *(float4*)&Vs[r * APAD + h8 * 8 + 4] = vhi;
        }
        if (tid < 64) ms[tid] = mask[b * S_ + kt + tid];
        __syncthreads();

        float s[8][4];
        #pragma unroll
        for (int ni = 0; ni < 8; ni++)
            #pragma unroll
            for (int j = 0; j < 4; j++) s[ni][j] = 0.f;

        #pragma unroll
        for (int ks = 0; ks < 8; ks++) {
            #pragma unroll
            for (int ni = 0; ni < 8; ni++) {
                const int nr = (ni * 8 + g) * APAD + ks * 8 + t;
                const uint32_t b0 = __float_as_uint(Ks[nr]);
                const uint32_t b1 = __float_as_uint(Ks[nr + 4]);
                mma_tf32(s[ni], qf[ks], b0, b1);
            }
        }

        float rmax0 = -1e30f, rmax1 = -1e30f;
        #pragma unroll
        for (int ni = 0; ni < 8; ni++) {
            const int col = ni * 8 + 2 * t;
            const int mz0 = ms[col], mz1 = ms[col + 1];
            float v0 = s[ni][0] * 0.125f; if (mz0 == 0) v0 = -1e9f;
            float v1 = s[ni][1] * 0.125f; if (mz1 == 0) v1 = -1e9f;
            float v2 = s[ni][2] * 0.125f; if (mz0 == 0) v2 = -1e9f;
            float v3 = s[ni][3] * 0.125f; if (mz1 == 0) v3 = -1e9f;
            s[ni][0] = v0; s[ni][1] = v1; s[ni][2] = v2; s[ni][3] = v3;
            rmax0 = fmaxf(rmax0, fmaxf(v0, v1));
            rmax1 = fmaxf(rmax1, fmaxf(v2, v3));
        }
        rmax0 = fmaxf(rmax0, __shfl_xor_sync(0xffffffffu, rmax0, 1));
        rmax0 = fmaxf(rmax0, __shfl_xor_sync(0xffffffffu, rmax0, 2));
        rmax1 = fmaxf(rmax1, __shfl_xor_sync(0xffffffffu, rmax1, 1));
        rmax1 = fmaxf(rmax1, __shfl_xor_sync(0xffffffffu, rmax1, 2));

        const float mn0 = fmaxf(m0, rmax0);
        const float mn1 = fmaxf(m1, rmax1);
        const float c0 = __expf(m0 - mn0);
        const float c1 = __expf(m1 - mn1);

        float rs0 = 0.f, rs1 = 0.f;
        #pragma unroll
        for (int ni = 0; ni < 8; ni++) {
            float p0 = __expf(s[ni][0] - mn0);
            float p1 = __expf(s[ni][1] - mn0);
            float p2 = __expf(s[ni][2] - mn1);
            float p3 = __expf(s[ni][3] - mn1);
            s[ni][0] = p0; s[ni][1] = p1; s[ni][2] = p2; s[ni][3] = p3;
            rs0 += p0 + p1;
            rs1 += p2 + p3;
        }
        rs0 += __shfl_xor_sync(0xffffffffu, rs0, 1);
        rs0 += __shfl_xor_sync(0xffffffffu, rs0, 2);
        rs1 += __shfl_xor_sync(0xffffffffu, rs1, 1);
        rs1 += __shfl_xor_sync(0xffffffffu, rs1, 2);

        l0 = l0 * c0 + rs0;
        l1 = l1 * c1 + rs1;
        #pragma unroll
        for (int ni = 0; ni < 8; ni++) {
            o[ni][0] *= c0; o[ni][1] *= c0;
            o[ni][2] *= c1; o[ni][3] *= c1;
        }
        m0 = mn0; m1 = mn1;

        #pragma unroll
        for (int ni = 0; ni < 8; ni++) {
            const int col = ni * 8 + 2 * t;
            myP[g * APAD + col]           = f2tf32f(s[ni][0]);
            myP[g * APAD + col + 1]       = f2tf32f(s[ni][1]);
            myP[(g + 8) * APAD + col]     = f2tf32f(s[ni][2]);
            myP[(g + 8) * APAD + col + 1] = f2tf32f(s[ni][3]);
        }
        __syncwarp();

        #pragma unroll
        for (int ks = 0; ks < 8; ks++) {
            uint32_t a[4];
            a[0] = __float_as_uint(myP[g * APAD + ks * 8 + t]);
            a[1] = __float_as_uint(myP[(g + 8) * APAD + ks * 8 + t]);
            a[2] = __float_as_uint(myP[g * APAD + ks * 8 + t + 4]);
            a[3] = __float_as_uint(myP[(g + 8) * APAD + ks * 8 + t + 4]);
            #pragma unroll
            for (int ni = 0; ni < 8; ni++) {
                const uint32_t b0 = __float_as_uint(Vs[(ks * 8 + t) * APAD + ni * 8 + g]);
                const uint32_t b1 = __float_as_uint(Vs[(ks * 8 + t + 4) * APAD + ni * 8 + g]);
                mma_tf32(o[ni], a, b0, b1);
            }
        }
        __syncwarp();
        __syncthreads();
    }

    const float inv0 = 1.f / l0;
    const float inv1 = 1.f / l1;
    const size_t r0 = (size_t)(b * S_ + q0 + mrow) * D_MODEL + h * HEAD_DIM;
    const size_t r1 = (size_t)(b * S_ + q0 + mrow + 8) * D_MODEL + h * HEAD_DIM;
    #pragma unroll
    for (int ni = 0; ni < 8; ni++) {
        const int col = ni * 8 + 2 * t;
        *(uint32_t*)&O[r0 + col] = pack_h2(o[ni][0] * inv0, o[ni][1] * inv0);
        *(uint32_t*)&O[r1 + col] = pack_h2(o[ni][2] * inv1, o[ni][3] * inv1);
    }
}

// ---------------------------------------------------------------------------
// Residual add + LayerNorm; optional fp16 second output
// ---------------------------------------------------------------------------
__global__ __launch_bounds__(256)
void add_ln_kernel(const float* __restrict__ X,
                   const float* __restrict__ Y,
                   const float* __restrict__ g,
                   const float* __restrict__ beta,
                   float* __restrict__ out,
                   __half* __restrict__ outh)
{
    const int row = blockIdx.x;
    const int t = threadIdx.x;
    const float4 a = ((const float4*)(X + (size_t)row * D_MODEL))[t];
    const float4 c = ((const float4*)(Y + (size_t)row * D_MODEL))[t];
    const float v0 = a.x + c.x, v1 = a.y + c.y, v2 = a.z + c.z, v3 = a.w + c.w;

    float s  = v0 + v1 + v2 + v3;
    float ss = v0 * v0 + v1 * v1 + v2 * v2 + v3 * v3;

    #pragma unroll
    for (int off = 16; off; off >>= 1) {
        s  += __shfl_xor_sync(0xffffffffu, s,  off);
        ss += __shfl_xor_sync(0xffffffffu, ss, off);
    }
    __shared__ float ws[8], wss[8];
    const int w = t >> 5;
    if ((t & 31) == 0) { ws[w] = s; wss[w] = ss; }
    __syncthreads();

    float stot = 0.f, sstot = 0.f;
    #pragma unroll
    for (int i = 0; i < 8; i++) { stot += ws[i]; sstot += wss[i]; }

    const float mean = stot * (1.f / 1024.f);
    const float var  = sstot * (1.f / 1024.f) - mean * mean;
    const float r    = rsqrtf(var + 1e-5f);

    const float4 gg = ((const float4*)g)[t];
    const float4 bb = ((const float4*)beta)[t];
    float4 o;
    o.x = (v0 - mean) * r * gg.x + bb.x;
    o.y = (v1 - mean) * r * gg.y + bb.y;
    o.z = (v2 - mean) * r * gg.z + bb.z;
    o.w = (v3 - mean) * r * gg.w + bb.w;
    ((float4*)(out + (size_t)row * D_MODEL))[t] = o;
    if (outh) {
        uint2 q;
        q.x = pack_h2(o.x, o.y);
        q.y = pack_h2(o.z, o.w);
        ((uint2*)(outh + (size_t)row * D_MODEL))[t] = q;
    }
}

// ---------------------------------------------------------------------------
// Launch — QKV GEMM is launch #4 (the profiled slot)
// ---------------------------------------------------------------------------
extern "C" void kernel_launch(void* const* d_in, const int* in_sizes, int n_in,
                              void* d_out, int out_size)
{
    const float* x    = (const float*)d_in[0];
    const int*   mask = (const int*)  d_in[1];
    const float* wq   = (const float*)d_in[2];
    const float* bq   = (const float*)d_in[3];
    const float* wk   = (const float*)d_in[4];
    const float* bk   = (const float*)d_in[5];
    const float* wv   = (const float*)d_in[6];
    const float* bv   = (const float*)d_in[7];
    const float* wo   = (const float*)d_in[8];
    const float* bo   = (const float*)d_in[9];
    const float* w1   = (const float*)d_in[10];
    const float* b1   = (const float*)d_in[11];
    const float* w2   = (const float*)d_in[12];
    const float* b2   = (const float*)d_in[13];
    const float* ln1g = (const float*)d_in[14];
    const float* ln1b = (const float*)d_in[15];
    const float* ln2g = (const float*)d_in[16];
    const float* ln2b = (const float*)d_in[17];

    __half *xh, *qkv, *ap, *x1h, *f1p;
    float *pp, *x1p, *f2p, *bqkv;
    __half *wqkvt, *wot, *w1t, *w2t;
    cudaGetSymbolAddress((void**)&xh,    g_xh);
    cudaGetSymbolAddress((void**)&qkv,   g_qkv);
    cudaGetSymbolAddress((void**)&ap,    g_attn);
    cudaGetSymbolAddress((void**)&pp,    g_proj);
    cudaGetSymbolAddress((void**)&x1p,   g_x1);
    cudaGetSymbolAddress((void**)&x1h,   g_x1h);
    cudaGetSymbolAddress((void**)&f1p,   g_ff1);
    cudaGetSymbolAddress((void**)&f2p,   g_ff2);
    cudaGetSymbolAddress((void**)&wqkvt, g_wqkvt);
    cudaGetSymbolAddress((void**)&wot,   g_wot);
    cudaGetSymbolAddress((void**)&w1t,   g_w1t);
    cudaGetSymbolAddress((void**)&w2t,   g_w2t);
    cudaGetSymbolAddress((void**)&bqkv,  g_bqkv);

    static int attr_set = 0;
    if (!attr_set) {
        cudaFuncSetAttribute(attn_tc_kernel,
                             cudaFuncAttributeMaxDynamicSharedMemorySize,
                             ATTN_SMEM_BYTES);
        attr_set = 1;
    }

    // 1-3: QKV GEMM dependencies
    transpose3_kernel<<<dim3(32, 32, 3), 256>>>(wq, wk, wv, wqkvt);
    pack_bias_kernel<<<QKV_N / 256, 256>>>(bq, bk, bv, bqkv);
    half_copy_kernel<<<ROWS * D_MODEL / 8 / 256, 256>>>(x, xh);

    // 4 (profiled): fused QKV GEMM [4096,1024] @ [1024,3072] -> half
    gemm_f16<<<dim3(QKV_N / 128, ROWS / 128), 128>>>(
        xh, wqkvt, bqkv, qkv, D_MODEL, QKV_N, 2);

    // remaining weight prep
    transpose_h_kernel<<<dim3(D_MODEL / 32, D_MODEL / 32), 256>>>(wo, wot, D_MODEL, D_MODEL);
    transpose_h_kernel<<<dim3(D_FF / 32,    D_MODEL / 32), 256>>>(w1, w1t, D_MODEL, D_FF);
    transpose_h_kernel<<<dim3(D_MODEL / 32, D_FF / 32),    256>>>(w2, w2t, D_FF, D_MODEL);

    attn_tc_kernel<<<dim3(S_ / 64, NUM_HEADS, B_), 128, ATTN_SMEM_BYTES>>>(
        qkv, mask, ap);

    gemm_f16<<<dim3(D_MODEL / 128, ROWS / 128), 128>>>(
        ap, wot, bo, pp, D_MODEL, D_MODEL, 0);
    add_ln_kernel<<<ROWS, 256>>>(x, pp, ln1g, ln1b, x1p, x1h);

    gemm_f16<<<dim3(D_FF / 128, ROWS / 128), 128>>>(
        x1h, w1t, b1, f1p, D_MODEL, D_FF, 1);
    gemm_f16<<<dim3(D_MODEL / 128, ROWS / 128), 128>>>(
        f1p, w2t, b2, f2p, D_FF, D_MODEL, 0);
    add_ln_kernel<<<ROWS, 256>>>(x1p, f2p, ln2g, ln2b, (float*)d_out, (__half*)0);
}

// round 9
// speedup vs baseline: 7.3021x; 1.2943x over previous
#include <cuda_runtime.h>
#include <cuda_fp16.h>
#include <cstdint>

#define D_MODEL   1024
#define NUM_HEADS 16
#define HEAD_DIM  64
#define D_FF      4096
#define B_        2
#define S_        2048
#define ROWS      (B_ * S_)   // 4096
#define QKV_N     (3 * D_MODEL)

// ---------------------------------------------------------------------------
// Scratch (device globals; no allocation allowed)
// ---------------------------------------------------------------------------
__device__ __half g_xh  [ROWS * D_MODEL];
__device__ __half g_qkv [ROWS * QKV_N];
__device__ __half g_attn[ROWS * D_MODEL];
__device__ float  g_proj[ROWS * D_MODEL];
__device__ float  g_x1  [ROWS * D_MODEL];
__device__ __half g_x1h [ROWS * D_MODEL];
__device__ __half g_ff1 [ROWS * D_FF];
__device__ float  g_ff2 [ROWS * D_MODEL];
__device__ __half g_wqkvt[QKV_N * D_MODEL];
__device__ __half g_wot  [D_MODEL * D_MODEL];
__device__ __half g_w1t  [D_FF * D_MODEL];
__device__ __half g_w2t  [D_MODEL * D_FF];
__device__ float  g_bqkv [QKV_N];

__device__ __forceinline__ uint32_t smem_u32(const void* p) {
    uint32_t a;
    asm("{ .reg .u64 t; cvta.to.shared.u64 t, %1; cvt.u32.u64 %0, t; }"
        : "=r"(a) : "l"(p));
    return a;
}
// fp16 mma m16n8k16, fp32 accum
__device__ __forceinline__ void mma_f16(float* d, const uint32_t* a,
                                        uint32_t b0, uint32_t b1) {
    asm volatile(
        "mma.sync.aligned.m16n8k16.row.col.f32.f16.f16.f32 "
        "{%0,%1,%2,%3}, {%4,%5,%6,%7}, {%8,%9}, {%0,%1,%2,%3};"
        : "+f"(d[0]), "+f"(d[1]), "+f"(d[2]), "+f"(d[3])
        : "r"(a[0]), "r"(a[1]), "r"(a[2]), "r"(a[3]), "r"(b0), "r"(b1));
}
#define CP16(dst, src) \
    asm volatile("cp.async.cg.shared.global [%0], [%1], 16;" \
                 :: "r"(dst), "l"(src) : "memory")
#define CP_COMMIT() asm volatile("cp.async.commit_group;" ::: "memory")
#define CP_WAIT1()  asm volatile("cp.async.wait_group 1;" ::: "memory")

__device__ __forceinline__ uint32_t pack_h2(float lo, float hi) {
    __half2 h = __floats2half2_rn(lo, hi);
    return *(uint32_t*)&h;
}

// ---------------------------------------------------------------------------
// Weight prep
// ---------------------------------------------------------------------------
__global__ __launch_bounds__(256)
void transpose3_kernel(const float* __restrict__ wq, const float* __restrict__ wk,
                       const float* __restrict__ wv, __half* __restrict__ out)
{
    __shared__ float t[32][33];
    const float* W = (blockIdx.z == 0) ? wq : (blockIdx.z == 1) ? wk : wv;
    __half* Wt = out + (size_t)blockIdx.z * D_MODEL * D_MODEL;
    const int bn = blockIdx.x * 32;
    const int bk = blockIdx.y * 32;
    const int x = threadIdx.x & 31;
    const int y = (threadIdx.x >> 5) * 4;
    #pragma unroll
    for (int i = 0; i < 4; i++)
        t[y + i][x] = W[(size_t)(bk + y + i) * D_MODEL + bn + x];
    __syncthreads();
    #pragma unroll
    for (int i = 0; i < 4; i++)
        Wt[(size_t)(bn + y + i) * D_MODEL + bk + x] = __float2half(t[x][y + i]);
}

__global__ __launch_bounds__(256)
void transpose_h_kernel(const float* __restrict__ W, __half* __restrict__ Wt,
                        int Kd, int N)
{
    __shared__ float t[32][33];
    const int bn = blockIdx.x * 32;
    const int bk = blockIdx.y * 32;
    const int x = threadIdx.x & 31;
    const int y = (threadIdx.x >> 5) * 4;
    #pragma unroll
    for (int i = 0; i < 4; i++)
        t[y + i][x] = W[(size_t)(bk + y + i) * N + bn + x];
    __syncthreads();
    #pragma unroll
    for (int i = 0; i < 4; i++)
        Wt[(size_t)(bn + y + i) * Kd + bk + x] = __float2half(t[x][y + i]);
}

__global__ __launch_bounds__(256)
void half_copy_kernel(const float* __restrict__ in, __half* __restrict__ out)
{
    const int i = blockIdx.x * 256 + threadIdx.x;
    float4 a = ((const float4*)in)[2 * i];
    float4 b = ((const float4*)in)[2 * i + 1];
    uint4 o;
    o.x = pack_h2(a.x, a.y); o.y = pack_h2(a.z, a.w);
    o.z = pack_h2(b.x, b.y); o.w = pack_h2(b.z, b.w);
    ((uint4*)out)[i] = o;
}

__global__ __launch_bounds__(256)
void pack_bias_kernel(const float* __restrict__ bq, const float* __restrict__ bk,
                      const float* __restrict__ bv, float* __restrict__ o)
{
    const int i = blockIdx.x * 256 + threadIdx.x;
    float v = (i < 1024) ? bq[i] : (i < 2048) ? bk[i - 1024] : bv[i - 2048];
    o[i] = v;
}

// ---------------------------------------------------------------------------
// fp16 mma.sync GEMM, BK=64: C = A[M,K] @ Bt[N,K]^T + bias.
// CTA 128x128x64, 4 warps (2Mx2N, warp 64x64), cp.async double-buffered.
// Dynamic SMEM: 2 stages x 2 operands x (128 rows x 36 words) = 73728 B.
// mode: 0 = f32 out; 1 = ReLU + half out; 2 = half out.
// ---------------------------------------------------------------------------
#define GSTR 36                  // words per smem row (32 data + 4 pad)
#define GOP  (128 * GSTR)        // words per operand tile = 4608
#define GEMM_SMEM_BYTES (4 * GOP * 4)   // 73728

__global__ __launch_bounds__(128)
void gemm_f16(const __half* __restrict__ A,
              const __half* __restrict__ Bt,
              const float* __restrict__ bias,
              void* __restrict__ Cv,
              int Kd, int N, int mode)
{
    extern __shared__ uint32_t smg[];
    const uint32_t sbase = smem_u32(smg);

    const int tid  = threadIdx.x;
    const int lane = tid & 31;
    const int wid  = tid >> 5;
    const int g = lane >> 2;
    const int t = lane & 3;
    const int wm = wid & 1;
    const int wn = wid >> 1;
    const int row0 = blockIdx.y * 128;
    const int col0 = blockIdx.x * 128;

    float acc[4][8][4];
    #pragma unroll
    for (int mi = 0; mi < 4; mi++)
        #pragma unroll
        for (int ni = 0; ni < 8; ni++)
            #pragma unroll
            for (int j = 0; j < 4; j++) acc[mi][ni][j] = 0.f;

    // cp.async: 1024 x 16B per operand per chunk; 128 thr x 8
    uint32_t sdst[8];
    const __half* aP[8];
    const __half* bP[8];
    #pragma unroll
    for (int i = 0; i < 8; i++) {
        const int slot = tid + i * 128;
        const int r = slot >> 3, q = slot & 7;
        sdst[i] = (uint32_t)(r * GSTR + q * 4) * 4u;
        aP[i] = A  + (size_t)(row0 + r) * Kd + q * 8;
        bP[i] = Bt + (size_t)(col0 + r) * Kd + q * 8;
    }

    const int NC = Kd >> 6;

    #pragma unroll
    for (int i = 0; i < 8; i++) {
        CP16(sbase + sdst[i], aP[i]);
        CP16(sbase + GOP * 4u + sdst[i], bP[i]);
    }
    CP_COMMIT();

    for (int c = 0; c < NC; c++) {
        if (c + 1 < NC) {
            const int ko = (c + 1) * 64;
            const uint32_t st = (uint32_t)((c + 1) & 1) * (2u * GOP * 4u);
            #pragma unroll
            for (int i = 0; i < 8; i++) {
                CP16(sbase + st + sdst[i], aP[i] + ko);
                CP16(sbase + st + GOP * 4u + sdst[i], bP[i] + ko);
            }
        }
        CP_COMMIT();
        CP_WAIT1();
        __syncthreads();

        const uint32_t* As = smg + (c & 1) * 2 * GOP;
        const uint32_t* Bs = As + GOP;

        #pragma unroll
        for (int ks = 0; ks < 4; ks++) {
            const int kb = ks * 8;
            uint32_t af[4][4];
            #pragma unroll
            for (int mi = 0; mi < 4; mi++) {
                const int m0 = wm * 64 + mi * 16 + g;
                af[mi][0] = As[m0 * GSTR + kb + t];
                af[mi][1] = As[(m0 + 8) * GSTR + kb + t];
                af[mi][2] = As[m0 * GSTR + kb + 4 + t];
                af[mi][3] = As[(m0 + 8) * GSTR + kb + 4 + t];
            }
            #pragma unroll
            for (int ni = 0; ni < 8; ni++) {
                const int n0 = wn * 64 + ni * 8 + g;
                const uint32_t b0 = Bs[n0 * GSTR + kb + t];
                const uint32_t b1 = Bs[n0 * GSTR + kb + 4 + t];
                #pragma unroll
                for (int mi = 0; mi < 4; mi++)
                    mma_f16(acc[mi][ni], af[mi], b0, b1);
            }
        }
        __syncthreads();
    }

    #pragma unroll
    for (int mi = 0; mi < 4; mi++) {
        const int r0 = row0 + wm * 64 + mi * 16 + g;
        #pragma unroll
        for (int ni = 0; ni < 8; ni++) {
            const int col = col0 + wn * 64 + ni * 8 + 2 * t;
            float2 bb = *(const float2*)&bias[col];
            float v00 = acc[mi][ni][0] + bb.x;
            float v01 = acc[mi][ni][1] + bb.y;
            float v10 = acc[mi][ni][2] + bb.x;
            float v11 = acc[mi][ni][3] + bb.y;
            if (mode == 0) {
                float* C = (float*)Cv;
                float2 o0 = {v00, v01}, o1 = {v10, v11};
                *(float2*)&C[(size_t)r0 * N + col]       = o0;
                *(float2*)&C[(size_t)(r0 + 8) * N + col] = o1;
            } else {
                if (mode == 1) {
                    v00 = fmaxf(v00, 0.f); v01 = fmaxf(v01, 0.f);
                    v10 = fmaxf(v10, 0.f); v11 = fmaxf(v11, 0.f);
                }
                __half* C = (__half*)Cv;
                *(uint32_t*)&C[(size_t)r0 * N + col]       = pack_h2(v00, v01);
                *(uint32_t*)&C[(size_t)(r0 + 8) * N + col] = pack_h2(v10, v11);
            }
        }
    }
}

// ---------------------------------------------------------------------------
// fp16 flash attention (R7 kernel, VSTR overflow FIXED: 40 -> 72).
// QKV packed half [ROWS, 3072]; output half.
// Qs/Ps & Ks: 64 rows x 44 words; VT: 32 rows x 72 words (needs 64 + pad,
// 72 ≡ 8 mod 32 makes hot-loop reads 8t+g bank-bijective).
// ---------------------------------------------------------------------------
#define ASTR 44
#define VSTR 72

__global__ __launch_bounds__(128)
void attn_f16(const __half* __restrict__ QKV,
              const int*   __restrict__ mask,
              __half* __restrict__ O)
{
    __shared__ uint32_t Qs[64 * ASTR];    // also P staging
    __shared__ uint32_t Ks[64 * ASTR];
    __shared__ uint32_t VT[32 * VSTR];
    __shared__ int ms[64];

    const int b  = blockIdx.z;
    const int h  = blockIdx.y;
    const int q0 = blockIdx.x * 64;
    const int tid  = threadIdx.x;
    const int lane = tid & 31;
    const int wid  = tid >> 5;
    const int g = lane >> 2;
    const int t = lane & 3;

    const int qc = h * HEAD_DIM;
    const int kc = D_MODEL + h * HEAD_DIM;
    const int vc = 2 * D_MODEL + h * HEAD_DIM;

    // ---- Stage Q (64 rows x 64 halfs) ----
    #pragma unroll
    for (int i = 0; i < 4; i++) {
        const int slot = tid + i * 128;
        const int r = slot >> 3, q8 = slot & 7;
        uint4 v = *(const uint4*)(QKV + (size_t)(b * S_ + q0 + r) * QKV_N + qc + q8 * 8);
        *(uint4*)&Qs[r * ASTR + q8 * 4] = v;
    }
    __syncthreads();

    const int mrow = wid * 16 + g;
    uint32_t qf[4][4];
    #pragma unroll
    for (int ks = 0; ks < 4; ks++) {
        qf[ks][0] = Qs[mrow * ASTR + ks * 8 + t];
        qf[ks][1] = Qs[(mrow + 8) * ASTR + ks * 8 + t];
        qf[ks][2] = Qs[mrow * ASTR + ks * 8 + 4 + t];
        qf[ks][3] = Qs[(mrow + 8) * ASTR + ks * 8 + 4 + t];
    }
    __syncthreads();

    float o[8][4];
    #pragma unroll
    for (int ni = 0; ni < 8; ni++)
        #pragma unroll
        for (int j = 0; j < 4; j++) o[ni][j] = 0.f;
    float m0 = -1e30f, m1 = -1e30f, l0 = 0.f, l1 = 0.f;

    uint32_t* myP = Qs + wid * 16 * ASTR;

    const int vj = tid & 31;             // k-pair index
    const int vdh = (tid >> 5) * 16;     // d-quarter

    for (int kt = 0; kt < S_; kt += 64) {
        // K tile
        #pragma unroll
        for (int i = 0; i < 4; i++) {
            const int slot = tid + i * 128;
            const int r = slot >> 3, q8 = slot & 7;
            uint4 v = *(const uint4*)(QKV + (size_t)(b * S_ + kt + r) * QKV_N + kc + q8 * 8);
            *(uint4*)&Ks[r * ASTR + q8 * 4] = v;
        }
        // V tile -> VT (zip rows 2j, 2j+1 into half2-per-k-pair words)
        {
            const __half* v0p = QKV + (size_t)(b * S_ + kt + 2 * vj) * QKV_N + vc + vdh;
            const __half* v1p = v0p + QKV_N;
            uint4 r0a = *(const uint4*)(v0p);
            uint4 r0b = *(const uint4*)(v0p + 8);
            uint4 r1a = *(const uint4*)(v1p);
            uint4 r1b = *(const uint4*)(v1p + 8);
            uint32_t* dst = &VT[vj * VSTR + vdh];
            uint4 z;
            z.x = __byte_perm(r0a.x, r1a.x, 0x5410);
            z.y = __byte_perm(r0a.x, r1a.x, 0x7632);
            z.z = __byte_perm(r0a.y, r1a.y, 0x5410);
            z.w = __byte_perm(r0a.y, r1a.y, 0x7632);
            *(uint4*)dst = z;
            z.x = __byte_perm(r0a.z, r1a.z, 0x5410);
            z.y = __byte_perm(r0a.z, r1a.z, 0x7632);
            z.z = __byte_perm(r0a.w, r1a.w, 0x5410);
            z.w = __byte_perm(r0a.w, r1a.w, 0x7632);
            *(uint4*)(dst + 4) = z;
            z.x = __byte_perm(r0b.x, r1b.x, 0x5410);
            z.y = __byte_perm(r0b.x, r1b.x, 0x7632);
            z.z = __byte_perm(r0b.y, r1b.y, 0x5410);
            z.w = __byte_perm(r0b.y, r1b.y, 0x7632);
            *(uint4*)(dst + 8) = z;
            z.x = __byte_perm(r0b.z, r1b.z, 0x5410);
            z.y = __byte_perm(r0b.z, r1b.z, 0x7632);
            z.z = __byte_perm(r0b.w, r1b.w, 0x5410);
            z.w = __byte_perm(r0b.w, r1b.w, 0x7632);
            *(uint4*)(dst + 12) = z;
        }
        if (tid < 64) ms[tid] = mask[b * S_ + kt + tid];
        __syncthreads();

        // S = Q @ K^T
        float s[8][4];
        #pragma unroll
        for (int ni = 0; ni < 8; ni++)
            #pragma unroll
            for (int j = 0; j < 4; j++) s[ni][j] = 0.f;

        #pragma unroll
        for (int ks = 0; ks < 4; ks++) {
            #pragma unroll
            for (int ni = 0; ni < 8; ni++) {
                const int n0 = ni * 8 + g;
                const uint32_t b0 = Ks[n0 * ASTR + ks * 8 + t];
                const uint32_t b1 = Ks[n0 * ASTR + ks * 8 + 4 + t];
                mma_f16(s[ni], qf[ks], b0, b1);
            }
        }

        // scale + mask + online softmax
        float rmax0 = -1e30f, rmax1 = -1e30f;
        #pragma unroll
        for (int ni = 0; ni < 8; ni++) {
            const int col = ni * 8 + 2 * t;
            const int mz0 = ms[col], mz1 = ms[col + 1];
            float v0 = s[ni][0] * 0.125f; if (mz0 == 0) v0 = -1e9f;
            float v1 = s[ni][1] * 0.125f; if (mz1 == 0) v1 = -1e9f;
            float v2 = s[ni][2] * 0.125f; if (mz0 == 0) v2 = -1e9f;
            float v3 = s[ni][3] * 0.125f; if (mz1 == 0) v3 = -1e9f;
            s[ni][0] = v0; s[ni][1] = v1; s[ni][2] = v2; s[ni][3] = v3;
            rmax0 = fmaxf(rmax0, fmaxf(v0, v1));
            rmax1 = fmaxf(rmax1, fmaxf(v2, v3));
        }
        rmax0 = fmaxf(rmax0, __shfl_xor_sync(0xffffffffu, rmax0, 1));
        rmax0 = fmaxf(rmax0, __shfl_xor_sync(0xffffffffu, rmax0, 2));
        rmax1 = fmaxf(rmax1, __shfl_xor_sync(0xffffffffu, rmax1, 1));
        rmax1 = fmaxf(rmax1, __shfl_xor_sync(0xffffffffu, rmax1, 2));

        const float mn0 = fmaxf(m0, rmax0);
        const float mn1 = fmaxf(m1, rmax1);
        const float c0 = __expf(m0 - mn0);
        const float c1 = __expf(m1 - mn1);

        float rs0 = 0.f, rs1 = 0.f;
        #pragma unroll
        for (int ni = 0; ni < 8; ni++) {
            float p0 = __expf(s[ni][0] - mn0);
            float p1 = __expf(s[ni][1] - mn0);
            float p2 = __expf(s[ni][2] - mn1);
            float p3 = __expf(s[ni][3] - mn1);
            s[ni][0] = p0; s[ni][1] = p1; s[ni][2] = p2; s[ni][3] = p3;
            rs0 += p0 + p1;
            rs1 += p2 + p3;
        }
        rs0 += __shfl_xor_sync(0xffffffffu, rs0, 1);
        rs0 += __shfl_xor_sync(0xffffffffu, rs0, 2);
        rs1 += __shfl_xor_sync(0xffffffffu, rs1, 1);
        rs1 += __shfl_xor_sync(0xffffffffu, rs1, 2);

        l0 = l0 * c0 + rs0;
        l1 = l1 * c1 + rs1;
        #pragma unroll
        for (int ni = 0; ni < 8; ni++) {
            o[ni][0] *= c0; o[ni][1] *= c0;
            o[ni][2] *= c1; o[ni][3] *= c1;
        }
        m0 = mn0; m1 = mn1;

        // P (half) -> per-warp smem; O += P @ V
        #pragma unroll
        for (int ni = 0; ni < 8; ni++) {
            myP[g * ASTR + ni * 4 + t]       = pack_h2(s[ni][0], s[ni][1]);
            myP[(g + 8) * ASTR + ni * 4 + t] = pack_h2(s[ni][2], s[ni][3]);
        }
        __syncwarp();

        #pragma unroll
        for (int ks = 0; ks < 4; ks++) {
            uint32_t a[4];
            a[0] = myP[g * ASTR + ks * 8 + t];
            a[1] = myP[(g + 8) * ASTR + ks * 8 + t];
            a[2] = myP[g * ASTR + ks * 8 + 4 + t];
            a[3] = myP[(g + 8) * ASTR + ks * 8 + 4 + t];
            #pragma unroll
            for (int ni = 0; ni < 8; ni++) {
                const uint32_t b0 = VT[(ks * 8 + t) * VSTR + ni * 8 + g];
                const uint32_t b1 = VT[(ks * 8 + 4 + t) * VSTR + ni * 8 + g];
                mma_f16(o[ni], a, b0, b1);
            }
        }
        __syncwarp();
        __syncthreads();
    }

    const float inv0 = 1.f / l0;
    const float inv1 = 1.f / l1;
    const size_t r0 = (size_t)(b * S_ + q0 + mrow) * D_MODEL + h * HEAD_DIM;
    const size_t r1 = (size_t)(b * S_ + q0 + mrow + 8) * D_MODEL + h * HEAD_DIM;
    #pragma unroll
    for (int ni = 0; ni < 8; ni++) {
        const int col = ni * 8 + 2 * t;
        *(uint32_t*)&O[r0 + col] = pack_h2(o[ni][0] * inv0, o[ni][1] * inv0);
        *(uint32_t*)&O[r1 + col] = pack_h2(o[ni][2] * inv1, o[ni][3] * inv1);
    }
}

// ---------------------------------------------------------------------------
// Residual add + LayerNorm; optional fp16 second output
// ---------------------------------------------------------------------------
__global__ __launch_bounds__(256)
void add_ln_kernel(const float* __restrict__ X,
                   const float* __restrict__ Y,
                   const float* __restrict__ g,
                   const float* __restrict__ beta,
                   float* __restrict__ out,
                   __half* __restrict__ outh)
{
    const int row = blockIdx.x;
    const int t = threadIdx.x;
    const float4 a = ((const float4*)(X + (size_t)row * D_MODEL))[t];
    const float4 c = ((const float4*)(Y + (size_t)row * D_MODEL))[t];
    const float v0 = a.x + c.x, v1 = a.y + c.y, v2 = a.z + c.z, v3 = a.w + c.w;

    float s  = v0 + v1 + v2 + v3;
    float ss = v0 * v0 + v1 * v1 + v2 * v2 + v3 * v3;

    #pragma unroll
    for (int off = 16; off; off >>= 1) {
        s  += __shfl_xor_sync(0xffffffffu, s,  off);
        ss += __shfl_xor_sync(0xffffffffu, ss, off);
    }
    __shared__ float ws[8], wss[8];
    const int w = t >> 5;
    if ((t & 31) == 0) { ws[w] = s; wss[w] = ss; }
    __syncthreads();

    float stot = 0.f, sstot = 0.f;
    #pragma unroll
    for (int i = 0; i < 8; i++) { stot += ws[i]; sstot += wss[i]; }

    const float mean = stot * (1.f / 1024.f);
    const float var  = sstot * (1.f / 1024.f) - mean * mean;
    const float r    = rsqrtf(var + 1e-5f);

    const float4 gg = ((const float4*)g)[t];
    const float4 bb = ((const float4*)beta)[t];
    float4 o;
    o.x = (v0 - mean) * r * gg.x + bb.x;
    o.y = (v1 - mean) * r * gg.y + bb.y;
    o.z = (v2 - mean) * r * gg.z + bb.z;
    o.w = (v3 - mean) * r * gg.w + bb.w;
    ((float4*)(out + (size_t)row * D_MODEL))[t] = o;
    if (outh) {
        uint2 q;
        q.x = pack_h2(o.x, o.y);
        q.y = pack_h2(o.z, o.w);
        ((uint2*)(outh + (size_t)row * D_MODEL))[t] = q;
    }
}

// ---------------------------------------------------------------------------
// Launch — QKV GEMM in profiled slot #4
// ---------------------------------------------------------------------------
extern "C" void kernel_launch(void* const* d_in, const int* in_sizes, int n_in,
                              void* d_out, int out_size)
{
    const float* x    = (const float*)d_in[0];
    const int*   mask = (const int*)  d_in[1];
    const float* wq   = (const float*)d_in[2];
    const float* bq   = (const float*)d_in[3];
    const float* wk   = (const float*)d_in[4];
    const float* bk   = (const float*)d_in[5];
    const float* wv   = (const float*)d_in[6];
    const float* bv   = (const float*)d_in[7];
    const float* wo   = (const float*)d_in[8];
    const float* bo   = (const float*)d_in[9];
    const float* w1   = (const float*)d_in[10];
    const float* b1   = (const float*)d_in[11];
    const float* w2   = (const float*)d_in[12];
    const float* b2   = (const float*)d_in[13];
    const float* ln1g = (const float*)d_in[14];
    const float* ln1b = (const float*)d_in[15];
    const float* ln2g = (const float*)d_in[16];
    const float* ln2b = (const float*)d_in[17];

    __half *xh, *qkv, *ap, *x1h, *f1p;
    float *pp, *x1p, *f2p, *bqkv;
    __half *wqkvt, *wot, *w1t, *w2t;
    cudaGetSymbolAddress((void**)&xh,    g_xh);
    cudaGetSymbolAddress((void**)&qkv,   g_qkv);
    cudaGetSymbolAddress((void**)&ap,    g_attn);
    cudaGetSymbolAddress((void**)&pp,    g_proj);
    cudaGetSymbolAddress((void**)&x1p,   g_x1);
    cudaGetSymbolAddress((void**)&x1h,   g_x1h);
    cudaGetSymbolAddress((void**)&f1p,   g_ff1);
    cudaGetSymbolAddress((void**)&f2p,   g_ff2);
    cudaGetSymbolAddress((void**)&wqkvt, g_wqkvt);
    cudaGetSymbolAddress((void**)&wot,   g_wot);
    cudaGetSymbolAddress((void**)&w1t,   g_w1t);
    cudaGetSymbolAddress((void**)&w2t,   g_w2t);
    cudaGetSymbolAddress((void**)&bqkv,  g_bqkv);

    static int attr_set = 0;
    if (!attr_set) {
        cudaFuncSetAttribute(gemm_f16,
                             cudaFuncAttributeMaxDynamicSharedMemorySize,
                             GEMM_SMEM_BYTES);
        attr_set = 1;
    }

    // 1-3: QKV GEMM dependencies
    transpose3_kernel<<<dim3(32, 32, 3), 256>>>(wq, wk, wv, wqkvt);
    pack_bias_kernel<<<QKV_N / 256, 256>>>(bq, bk, bv, bqkv);
    half_copy_kernel<<<ROWS * D_MODEL / 8 / 256, 256>>>(x, xh);

    // 4 (profiled): fused QKV GEMM
    gemm_f16<<<dim3(QKV_N / 128, ROWS / 128), 128, GEMM_SMEM_BYTES>>>(
        xh, wqkvt, bqkv, qkv, D_MODEL, QKV_N, 2);

    transpose_h_kernel<<<dim3(D_MODEL / 32, D_MODEL / 32), 256>>>(wo, wot, D_MODEL, D_MODEL);
    transpose_h_kernel<<<dim3(D_FF / 32,    D_MODEL / 32), 256>>>(w1, w1t, D_MODEL, D_FF);
    transpose_h_kernel<<<dim3(D_MODEL / 32, D_FF / 32),    256>>>(w2, w2t, D_FF, D_MODEL);

    attn_f16<<<dim3(S_ / 64, NUM_HEADS, B_), 128>>>(qkv, mask, ap);

    gemm_f16<<<dim3(D_MODEL / 128, ROWS / 128), 128, GEMM_SMEM_BYTES>>>(
        ap, wot, bo, pp, D_MODEL, D_MODEL, 0);
    add_ln_kernel<<<ROWS, 256>>>(x, pp, ln1g, ln1b, x1p, x1h);

    gemm_f16<<<dim3(D_FF / 128, ROWS / 128), 128, GEMM_SMEM_BYTES>>>(
        x1h, w1t, b1, f1p, D_MODEL, D_FF, 1);
    gemm_f16<<<dim3(D_MODEL / 128, ROWS / 128), 128, GEMM_SMEM_BYTES>>>(
        f1p, w2t, b2, f2p, D_FF, D_MODEL, 0);
    add_ln_kernel<<<ROWS, 256>>>(x1p, f2p, ln2g, ln2b, (float*)d_out, (__half*)0);
}

// round 10
// speedup vs baseline: 7.4207x; 1.0162x over previous
#include <cuda_runtime.h>
#include <cuda_fp16.h>
#include <cstdint>

#define D_MODEL   1024
#define NUM_HEADS 16
#define HEAD_DIM  64
#define D_FF      4096
#define B_        2
#define S_        2048
#define ROWS      (B_ * S_)   // 4096
#define QKV_N     (3 * D_MODEL)

// ---------------------------------------------------------------------------
// Scratch (device globals; no allocation allowed)
// ---------------------------------------------------------------------------
__device__ __half g_xh  [ROWS * D_MODEL];
__device__ __half g_qkv [ROWS * QKV_N];
__device__ __half g_attn[ROWS * D_MODEL];
__device__ float  g_proj[ROWS * D_MODEL];
__device__ float  g_x1  [ROWS * D_MODEL];
__device__ __half g_x1h [ROWS * D_MODEL];
__device__ __half g_ff1 [ROWS * D_FF];
__device__ float  g_ff2 [ROWS * D_MODEL];
__device__ __half g_wqkvt[QKV_N * D_MODEL];
__device__ __half g_wot  [D_MODEL * D_MODEL];
__device__ __half g_w1t  [D_FF * D_MODEL];
__device__ __half g_w2t  [D_MODEL * D_FF];
__device__ float  g_bqkv [QKV_N];

__device__ __forceinline__ uint32_t smem_u32(const void* p) {
    uint32_t a;
    asm("{ .reg .u64 t; cvta.to.shared.u64 t, %1; cvt.u32.u64 %0, t; }"
        : "=r"(a) : "l"(p));
    return a;
}
// fp16 mma m16n8k16, fp32 accum
__device__ __forceinline__ void mma_f16(float* d, const uint32_t* a,
                                        uint32_t b0, uint32_t b1) {
    asm volatile(
        "mma.sync.aligned.m16n8k16.row.col.f32.f16.f16.f32 "
        "{%0,%1,%2,%3}, {%4,%5,%6,%7}, {%8,%9}, {%0,%1,%2,%3};"
        : "+f"(d[0]), "+f"(d[1]), "+f"(d[2]), "+f"(d[3])
        : "r"(a[0]), "r"(a[1]), "r"(a[2]), "r"(a[3]), "r"(b0), "r"(b1));
}
#define LDSM_X4(R0, R1, R2, R3, saddr) \
    asm volatile("ldmatrix.sync.aligned.m8n8.x4.shared.b16 {%0,%1,%2,%3}, [%4];" \
        : "=r"(R0), "=r"(R1), "=r"(R2), "=r"(R3) : "r"(saddr))
#define CP16(dst, src) \
    asm volatile("cp.async.cg.shared.global [%0], [%1], 16;" \
                 :: "r"(dst), "l"(src) : "memory")
#define CP_COMMIT() asm volatile("cp.async.commit_group;" ::: "memory")
#define CP_WAIT1()  asm volatile("cp.async.wait_group 1;" ::: "memory")

__device__ __forceinline__ uint32_t pack_h2(float lo, float hi) {
    __half2 h = __floats2half2_rn(lo, hi);
    return *(uint32_t*)&h;
}

// ---------------------------------------------------------------------------
// Weight prep
// ---------------------------------------------------------------------------
__global__ __launch_bounds__(256)
void transpose3_kernel(const float* __restrict__ wq, const float* __restrict__ wk,
                       const float* __restrict__ wv, __half* __restrict__ out)
{
    __shared__ float t[32][33];
    const float* W = (blockIdx.z == 0) ? wq : (blockIdx.z == 1) ? wk : wv;
    __half* Wt = out + (size_t)blockIdx.z * D_MODEL * D_MODEL;
    const int bn = blockIdx.x * 32;
    const int bk = blockIdx.y * 32;
    const int x = threadIdx.x & 31;
    const int y = (threadIdx.x >> 5) * 4;
    #pragma unroll
    for (int i = 0; i < 4; i++)
        t[y + i][x] = W[(size_t)(bk + y + i) * D_MODEL + bn + x];
    __syncthreads();
    #pragma unroll
    for (int i = 0; i < 4; i++)
        Wt[(size_t)(bn + y + i) * D_MODEL + bk + x] = __float2half(t[x][y + i]);
}

__global__ __launch_bounds__(256)
void transpose_h_kernel(const float* __restrict__ W, __half* __restrict__ Wt,
                        int Kd, int N)
{
    __shared__ float t[32][33];
    const int bn = blockIdx.x * 32;
    const int bk = blockIdx.y * 32;
    const int x = threadIdx.x & 31;
    const int y = (threadIdx.x >> 5) * 4;
    #pragma unroll
    for (int i = 0; i < 4; i++)
        t[y + i][x] = W[(size_t)(bk + y + i) * N + bn + x];
    __syncthreads();
    #pragma unroll
    for (int i = 0; i < 4; i++)
        Wt[(size_t)(bn + y + i) * Kd + bk + x] = __float2half(t[x][y + i]);
}

__global__ __launch_bounds__(256)
void half_copy_kernel(const float* __restrict__ in, __half* __restrict__ out)
{
    const int i = blockIdx.x * 256 + threadIdx.x;
    float4 a = ((const float4*)in)[2 * i];
    float4 b = ((const float4*)in)[2 * i + 1];
    uint4 o;
    o.x = pack_h2(a.x, a.y); o.y = pack_h2(a.z, a.w);
    o.z = pack_h2(b.x, b.y); o.w = pack_h2(b.z, b.w);
    ((uint4*)out)[i] = o;
}

__global__ __launch_bounds__(256)
void pack_bias_kernel(const float* __restrict__ bq, const float* __restrict__ bk,
                      const float* __restrict__ bv, float* __restrict__ o)
{
    const int i = blockIdx.x * 256 + threadIdx.x;
    float v = (i < 1024) ? bq[i] : (i < 2048) ? bk[i - 1024] : bv[i - 2048];
    o[i] = v;
}

// ---------------------------------------------------------------------------
// fp16 mma.sync GEMM, BK=64, ldmatrix fragment loads.
// CTA 128x128x64, 4 warps (2Mx2N, warp 64x64), cp.async double-buffered.
// Dynamic SMEM: 2 stages x 2 operands x (128 x 36 words) = 73728 B.
// GSTR=36 -> row stride 144B == 16 mod 128: ldmatrix phases conflict-free.
// mode: 0 = f32 out; 1 = ReLU + half out; 2 = half out.
// ---------------------------------------------------------------------------
#define GSTR 36
#define GOP  (128 * GSTR)
#define GEMM_SMEM_BYTES (4 * GOP * 4)   // 73728

__global__ __launch_bounds__(128)
void gemm_f16(const __half* __restrict__ A,
              const __half* __restrict__ Bt,
              const float* __restrict__ bias,
              void* __restrict__ Cv,
              int Kd, int N, int mode)
{
    extern __shared__ uint32_t smg[];
    const uint32_t sbase = smem_u32(smg);

    const int tid  = threadIdx.x;
    const int lane = tid & 31;
    const int wid  = tid >> 5;
    const int g = lane >> 2;
    const int t = lane & 3;
    const int wm = wid & 1;
    const int wn = wid >> 1;
    const int row0 = blockIdx.y * 128;
    const int col0 = blockIdx.x * 128;

    float acc[4][8][4];
    #pragma unroll
    for (int mi = 0; mi < 4; mi++)
        #pragma unroll
        for (int ni = 0; ni < 8; ni++)
            #pragma unroll
            for (int j = 0; j < 4; j++) acc[mi][ni][j] = 0.f;

    // cp.async mapping: 1024 x 16B per operand per chunk; 128 thr x 8
    uint32_t sdst[8];
    const __half* aP[8];
    const __half* bP[8];
    #pragma unroll
    for (int i = 0; i < 8; i++) {
        const int slot = tid + i * 128;
        const int r = slot >> 3, q = slot & 7;
        sdst[i] = (uint32_t)(r * GSTR + q * 4) * 4u;
        aP[i] = A  + (size_t)(row0 + r) * Kd + q * 8;
        bP[i] = Bt + (size_t)(col0 + r) * Kd + q * 8;
    }

    // ldmatrix per-lane base addresses (byte offsets within a stage)
    // A: lanes 0-7 -> rows m0..+7 @kb; 8-15 -> rows+8 @kb; 16-23 -> rows @kb+8h; 24-31 -> rows+8 @kb+8h
    const int lane7 = lane & 7;
    const uint32_t aRow  = (uint32_t)(wm * 64 + lane7 + (lane & 8));
    const uint32_t aColW = (uint32_t)((lane >> 4) * 4);         // +8 halfs
    const uint32_t aOffB = (aRow * GSTR + aColW) * 4u;
    // B: lanes 0-7 -> n0..+7 @kb; 8-15 -> n0..+7 @kb+8h; 16-23 -> n0+8..15 @kb; 24-31 -> +8 @kb+8h
    const uint32_t bRow  = (uint32_t)(wn * 64 + lane7 + ((lane >> 4) & 1) * 8);
    const uint32_t bColW = (uint32_t)(((lane >> 3) & 1) * 4);
    const uint32_t bOffB = (bRow * GSTR + bColW) * 4u + GOP * 4u;

    const int NC = Kd >> 6;

    #pragma unroll
    for (int i = 0; i < 8; i++) {
        CP16(sbase + sdst[i], aP[i]);
        CP16(sbase + GOP * 4u + sdst[i], bP[i]);
    }
    CP_COMMIT();

    for (int c = 0; c < NC; c++) {
        if (c + 1 < NC) {
            const int ko = (c + 1) * 64;
            const uint32_t st = (uint32_t)((c + 1) & 1) * (2u * GOP * 4u);
            #pragma unroll
            for (int i = 0; i < 8; i++) {
                CP16(sbase + st + sdst[i], aP[i] + ko);
                CP16(sbase + st + GOP * 4u + sdst[i], bP[i] + ko);
            }
        }
        CP_COMMIT();
        CP_WAIT1();
        __syncthreads();

        const uint32_t stg = sbase + (uint32_t)(c & 1) * (2u * GOP * 4u);
        const uint32_t aBase = stg + aOffB;
        const uint32_t bBase = stg + bOffB;

        #pragma unroll
        for (int ks = 0; ks < 4; ks++) {
            const uint32_t kOff = (uint32_t)(ks * 8) * 4u;   // 8 words per k-step

            uint32_t af[4][4];
            #pragma unroll
            for (int mi = 0; mi < 4; mi++) {
                LDSM_X4(af[mi][0], af[mi][1], af[mi][2], af[mi][3],
                        aBase + (uint32_t)(mi * 16 * GSTR) * 4u + kOff);
            }
            uint32_t bf[8][2];
            #pragma unroll
            for (int pr = 0; pr < 4; pr++) {
                LDSM_X4(bf[2 * pr][0], bf[2 * pr][1], bf[2 * pr + 1][0], bf[2 * pr + 1][1],
                        bBase + (uint32_t)(pr * 16 * GSTR) * 4u + kOff);
            }
            #pragma unroll
            for (int ni = 0; ni < 8; ni++)
                #pragma unroll
                for (int mi = 0; mi < 4; mi++)
                    mma_f16(acc[mi][ni], af[mi], bf[ni][0], bf[ni][1]);
        }
        __syncthreads();
    }

    #pragma unroll
    for (int mi = 0; mi < 4; mi++) {
        const int r0 = row0 + wm * 64 + mi * 16 + g;
        #pragma unroll
        for (int ni = 0; ni < 8; ni++) {
            const int col = col0 + wn * 64 + ni * 8 + 2 * t;
            float2 bb = *(const float2*)&bias[col];
            float v00 = acc[mi][ni][0] + bb.x;
            float v01 = acc[mi][ni][1] + bb.y;
            float v10 = acc[mi][ni][2] + bb.x;
            float v11 = acc[mi][ni][3] + bb.y;
            if (mode == 0) {
                float* C = (float*)Cv;
                float2 o0 = {v00, v01}, o1 = {v10, v11};
                *(float2*)&C[(size_t)r0 * N + col]       = o0;
                *(float2*)&C[(size_t)(r0 + 8) * N + col] = o1;
            } else {
                if (mode == 1) {
                    v00 = fmaxf(v00, 0.f); v01 = fmaxf(v01, 0.f);
                    v10 = fmaxf(v10, 0.f); v11 = fmaxf(v11, 0.f);
                }
                __half* C = (__half*)Cv;
                *(uint32_t*)&C[(size_t)r0 * N + col]       = pack_h2(v00, v01);
                *(uint32_t*)&C[(size_t)(r0 + 8) * N + col] = pack_h2(v10, v11);
            }
        }
    }
}

// ---------------------------------------------------------------------------
// fp16 flash attention (unchanged from R9 — proven correct).
// ---------------------------------------------------------------------------
#define ASTR 44
#define VSTR 72

__global__ __launch_bounds__(128)
void attn_f16(const __half* __restrict__ QKV,
              const int*   __restrict__ mask,
              __half* __restrict__ O)
{
    __shared__ uint32_t Qs[64 * ASTR];    // also P staging
    __shared__ uint32_t Ks[64 * ASTR];
    __shared__ uint32_t VT[32 * VSTR];
    __shared__ int ms[64];

    const int b  = blockIdx.z;
    const int h  = blockIdx.y;
    const int q0 = blockIdx.x * 64;
    const int tid  = threadIdx.x;
    const int lane = tid & 31;
    const int wid  = tid >> 5;
    const int g = lane >> 2;
    const int t = lane & 3;

    const int qc = h * HEAD_DIM;
    const int kc = D_MODEL + h * HEAD_DIM;
    const int vc = 2 * D_MODEL + h * HEAD_DIM;

    #pragma unroll
    for (int i = 0; i < 4; i++) {
        const int slot = tid + i * 128;
        const int r = slot >> 3, q8 = slot & 7;
        uint4 v = *(const uint4*)(QKV + (size_t)(b * S_ + q0 + r) * QKV_N + qc + q8 * 8);
        *(uint4*)&Qs[r * ASTR + q8 * 4] = v;
    }
    __syncthreads();

    const int mrow = wid * 16 + g;
    uint32_t qf[4][4];
    #pragma unroll
    for (int ks = 0; ks < 4; ks++) {
        qf[ks][0] = Qs[mrow * ASTR + ks * 8 + t];
        qf[ks][1] = Qs[(mrow + 8) * ASTR + ks * 8 + t];
        qf[ks][2] = Qs[mrow * ASTR + ks * 8 + 4 + t];
        qf[ks][3] = Qs[(mrow + 8) * ASTR + ks * 8 + 4 + t];
    }
    __syncthreads();

    float o[8][4];
    #pragma unroll
    for (int ni = 0; ni < 8; ni++)
        #pragma unroll
        for (int j = 0; j < 4; j++) o[ni][j] = 0.f;
    float m0 = -1e30f, m1 = -1e30f, l0 = 0.f, l1 = 0.f;

    uint32_t* myP = Qs + wid * 16 * ASTR;

    const int vj = tid & 31;
    const int vdh = (tid >> 5) * 16;

    for (int kt = 0; kt < S_; kt += 64) {
        #pragma unroll
        for (int i = 0; i < 4; i++) {
            const int slot = tid + i * 128;
            const int r = slot >> 3, q8 = slot & 7;
            uint4 v = *(const uint4*)(QKV + (size_t)(b * S_ + kt + r) * QKV_N + kc + q8 * 8);
            *(uint4*)&Ks[r * ASTR + q8 * 4] = v;
        }
        {
            const __half* v0p = QKV + (size_t)(b * S_ + kt + 2 * vj) * QKV_N + vc + vdh;
            const __half* v1p = v0p + QKV_N;
            uint4 r0a = *(const uint4*)(v0p);
            uint4 r0b = *(const uint4*)(v0p + 8);
            uint4 r1a = *(const uint4*)(v1p);
            uint4 r1b = *(const uint4*)(v1p + 8);
            uint32_t* dst = &VT[vj * VSTR + vdh];
            uint4 z;
            z.x = __byte_perm(r0a.x, r1a.x, 0x5410);
            z.y = __byte_perm(r0a.x, r1a.x, 0x7632);
            z.z = __byte_perm(r0a.y, r1a.y, 0x5410);
            z.w = __byte_perm(r0a.y, r1a.y, 0x7632);
            *(uint4*)dst = z;
            z.x = __byte_perm(r0a.z, r1a.z, 0x5410);
            z.y = __byte_perm(r0a.z, r1a.z, 0x7632);
            z.z = __byte_perm(r0a.w, r1a.w, 0x5410);
            z.w = __byte_perm(r0a.w, r1a.w, 0x7632);
            *(uint4*)(dst + 4) = z;
            z.x = __byte_perm(r0b.x, r1b.x, 0x5410);
            z.y = __byte_perm(r0b.x, r1b.x, 0x7632);
            z.z = __byte_perm(r0b.y, r1b.y, 0x5410);
            z.w = __byte_perm(r0b.y, r1b.y, 0x7632);
            *(uint4*)(dst + 8) = z;
            z.x = __byte_perm(r0b.z, r1b.z, 0x5410);
            z.y = __byte_perm(r0b.z, r1b.z, 0x7632);
            z.z = __byte_perm(r0b.w, r1b.w, 0x5410);
            z.w = __byte_perm(r0b.w, r1b.w, 0x7632);
            *(uint4*)(dst + 12) = z;
        }
        if (tid < 64) ms[tid] = mask[b * S_ + kt + tid];
        __syncthreads();

        float s[8][4];
        #pragma unroll
        for (int ni = 0; ni < 8; ni++)
            #pragma unroll
            for (int j = 0; j < 4; j++) s[ni][j] = 0.f;

        #pragma unroll
        for (int ks = 0; ks < 4; ks++) {
            #pragma unroll
            for (int ni = 0; ni < 8; ni++) {
                const int n0 = ni * 8 + g;
                const uint32_t b0 = Ks[n0 * ASTR + ks * 8 + t];
                const uint32_t b1 = Ks[n0 * ASTR + ks * 8 + 4 + t];
                mma_f16(s[ni], qf[ks], b0, b1);
            }
        }

        float rmax0 = -1e30f, rmax1 = -1e30f;
        #pragma unroll
        for (int ni = 0; ni < 8; ni++) {
            const int col = ni * 8 + 2 * t;
            const int mz0 = ms[col], mz1 = ms[col + 1];
            float v0 = s[ni][0] * 0.125f; if (mz0 == 0) v0 = -1e9f;
            float v1 = s[ni][1] * 0.125f; if (mz1 == 0) v1 = -1e9f;
            float v2 = s[ni][2] * 0.125f; if (mz0 == 0) v2 = -1e9f;
            float v3 = s[ni][3] * 0.125f; if (mz1 == 0) v3 = -1e9f;
            s[ni][0] = v0; s[ni][1] = v1; s[ni][2] = v2; s[ni][3] = v3;
            rmax0 = fmaxf(rmax0, fmaxf(v0, v1));
            rmax1 = fmaxf(rmax1, fmaxf(v2, v3));
        }
        rmax0 = fmaxf(rmax0, __shfl_xor_sync(0xffffffffu, rmax0, 1));
        rmax0 = fmaxf(rmax0, __shfl_xor_sync(0xffffffffu, rmax0, 2));
        rmax1 = fmaxf(rmax1, __shfl_xor_sync(0xffffffffu, rmax1, 1));
        rmax1 = fmaxf(rmax1, __shfl_xor_sync(0xffffffffu, rmax1, 2));

        const float mn0 = fmaxf(m0, rmax0);
        const float mn1 = fmaxf(m1, rmax1);
        const float c0 = __expf(m0 - mn0);
        const float c1 = __expf(m1 - mn1);

        float rs0 = 0.f, rs1 = 0.f;
        #pragma unroll
        for (int ni = 0; ni < 8; ni++) {
            float p0 = __expf(s[ni][0] - mn0);
            float p1 = __expf(s[ni][1] - mn0);
            float p2 = __expf(s[ni][2] - mn1);
            float p3 = __expf(s[ni][3] - mn1);
            s[ni][0] = p0; s[ni][1] = p1; s[ni][2] = p2; s[ni][3] = p3;
            rs0 += p0 + p1;
            rs1 += p2 + p3;
        }
        rs0 += __shfl_xor_sync(0xffffffffu, rs0, 1);
        rs0 += __shfl_xor_sync(0xffffffffu, rs0, 2);
        rs1 += __shfl_xor_sync(0xffffffffu, rs1, 1);
        rs1 += __shfl_xor_sync(0xffffffffu, rs1, 2);

        l0 = l0 * c0 + rs0;
        l1 = l1 * c1 + rs1;
        #pragma unroll
        for (int ni = 0; ni < 8; ni++) {
            o[ni][0] *= c0; o[ni][1] *= c0;
            o[ni][2] *= c1; o[ni][3] *= c1;
        }
        m0 = mn0; m1 = mn1;

        #pragma unroll
        for (int ni = 0; ni < 8; ni++) {
            myP[g * ASTR + ni * 4 + t]       = pack_h2(s[ni][0], s[ni][1]);
            myP[(g + 8) * ASTR + ni * 4 + t] = pack_h2(s[ni][2], s[ni][3]);
        }
        __syncwarp();

        #pragma unroll
        for (int ks = 0; ks < 4; ks++) {
            uint32_t a[4];
            a[0] = myP[g * ASTR + ks * 8 + t];
            a[1] = myP[(g + 8) * ASTR + ks * 8 + t];
            a[2] = myP[g * ASTR + ks * 8 + 4 + t];
            a[3] = myP[(g + 8) * ASTR + ks * 8 + 4 + t];
            #pragma unroll
            for (int ni = 0; ni < 8; ni++) {
                const uint32_t b0 = VT[(ks * 8 + t) * VSTR + ni * 8 + g];
                const uint32_t b1 = VT[(ks * 8 + 4 + t) * VSTR + ni * 8 + g];
                mma_f16(o[ni], a, b0, b1);
            }
        }
        __syncwarp();
        __syncthreads();
    }

    const float inv0 = 1.f / l0;
    const float inv1 = 1.f / l1;
    const size_t r0 = (size_t)(b * S_ + q0 + mrow) * D_MODEL + h * HEAD_DIM;
    const size_t r1 = (size_t)(b * S_ + q0 + mrow + 8) * D_MODEL + h * HEAD_DIM;
    #pragma unroll
    for (int ni = 0; ni < 8; ni++) {
        const int col = ni * 8 + 2 * t;
        *(uint32_t*)&O[r0 + col] = pack_h2(o[ni][0] * inv0, o[ni][1] * inv0);
        *(uint32_t*)&O[r1 + col] = pack_h2(o[ni][2] * inv1, o[ni][3] * inv1);
    }
}

// ---------------------------------------------------------------------------
// Residual add + LayerNorm; optional fp16 second output
// ---------------------------------------------------------------------------
__global__ __launch_bounds__(256)
void add_ln_kernel(const float* __restrict__ X,
                   const float* __restrict__ Y,
                   const float* __restrict__ g,
                   const float* __restrict__ beta,
                   float* __restrict__ out,
                   __half* __restrict__ outh)
{
    const int row = blockIdx.x;
    const int t = threadIdx.x;
    const float4 a = ((const float4*)(X + (size_t)row * D_MODEL))[t];
    const float4 c = ((const float4*)(Y + (size_t)row * D_MODEL))[t];
    const float v0 = a.x + c.x, v1 = a.y + c.y, v2 = a.z + c.z, v3 = a.w + c.w;

    float s  = v0 + v1 + v2 + v3;
    float ss = v0 * v0 + v1 * v1 + v2 * v2 + v3 * v3;

    #pragma unroll
    for (int off = 16; off; off >>= 1) {
        s  += __shfl_xor_sync(0xffffffffu, s,  off);
        ss += __shfl_xor_sync(0xffffffffu, ss, off);
    }
    __shared__ float ws[8], wss[8];
    const int w = t >> 5;
    if ((t & 31) == 0) { ws[w] = s; wss[w] = ss; }
    __syncthreads();

    float stot = 0.f, sstot = 0.f;
    #pragma unroll
    for (int i = 0; i < 8; i++) { stot += ws[i]; sstot += wss[i]; }

    const float mean = stot * (1.f / 1024.f);
    const float var  = sstot * (1.f / 1024.f) - mean * mean;
    const float r    = rsqrtf(var + 1e-5f);

    const float4 gg = ((const float4*)g)[t];
    const float4 bb = ((const float4*)beta)[t];
    float4 o;
    o.x = (v0 - mean) * r * gg.x + bb.x;
    o.y = (v1 - mean) * r * gg.y + bb.y;
    o.z = (v2 - mean) * r * gg.z + bb.z;
    o.w = (v3 - mean) * r * gg.w + bb.w;
    ((float4*)(out + (size_t)row * D_MODEL))[t] = o;
    if (outh) {
        uint2 q;
        q.x = pack_h2(o.x, o.y);
        q.y = pack_h2(o.z, o.w);
        ((uint2*)(outh + (size_t)row * D_MODEL))[t] = q;
    }
}

// ---------------------------------------------------------------------------
// Launch — QKV GEMM in profiled slot #4
// ---------------------------------------------------------------------------
extern "C" void kernel_launch(void* const* d_in, const int* in_sizes, int n_in,
                              void* d_out, int out_size)
{
    const float* x    = (const float*)d_in[0];
    const int*   mask = (const int*)  d_in[1];
    const float* wq   = (const float*)d_in[2];
    const float* bq   = (const float*)d_in[3];
    const float* wk   = (const float*)d_in[4];
    const float* bk   = (const float*)d_in[5];
    const float* wv   = (const float*)d_in[6];
    const float* bv   = (const float*)d_in[7];
    const float* wo   = (const float*)d_in[8];
    const float* bo   = (const float*)d_in[9];
    const float* w1   = (const float*)d_in[10];
    const float* b1   = (const float*)d_in[11];
    const float* w2   = (const float*)d_in[12];
    const float* b2   = (const float*)d_in[13];
    const float* ln1g = (const float*)d_in[14];
    const float* ln1b = (const float*)d_in[15];
    const float* ln2g = (const float*)d_in[16];
    const float* ln2b = (const float*)d_in[17];

    __half *xh, *qkv, *ap, *x1h, *f1p;
    float *pp, *x1p, *f2p, *bqkv;
    __half *wqkvt, *wot, *w1t, *w2t;
    cudaGetSymbolAddress((void**)&xh,    g_xh);
    cudaGetSymbolAddress((void**)&qkv,   g_qkv);
    cudaGetSymbolAddress((void**)&ap,    g_attn);
    cudaGetSymbolAddress((void**)&pp,    g_proj);
    cudaGetSymbolAddress((void**)&x1p,   g_x1);
    cudaGetSymbolAddress((void**)&x1h,   g_x1h);
    cudaGetSymbolAddress((void**)&f1p,   g_ff1);
    cudaGetSymbolAddress((void**)&f2p,   g_ff2);
    cudaGetSymbolAddress((void**)&wqkvt, g_wqkvt);
    cudaGetSymbolAddress((void**)&wot,   g_wot);
    cudaGetSymbolAddress((void**)&w1t,   g_w1t);
    cudaGetSymbolAddress((void**)&w2t,   g_w2t);
    cudaGetSymbolAddress((void**)&bqkv,  g_bqkv);

    static int attr_set = 0;
    if (!attr_set) {
        cudaFuncSetAttribute(gemm_f16,
                             cudaFuncAttributeMaxDynamicSharedMemorySize,
                             GEMM_SMEM_BYTES);
        cudaFuncSetAttribute(gemm_f16,
                             cudaFuncAttributePreferredSharedMemoryCarveout,
                             cudaSharedmemCarveoutMaxShared);
        attr_set = 1;
    }

    // 1-3: QKV GEMM dependencies
    transpose3_kernel<<<dim3(32, 32, 3), 256>>>(wq, wk, wv, wqkvt);
    pack_bias_kernel<<<QKV_N / 256, 256>>>(bq, bk, bv, bqkv);
    half_copy_kernel<<<ROWS * D_MODEL / 8 / 256, 256>>>(x, xh);

    // 4 (profiled): fused QKV GEMM
    gemm_f16<<<dim3(QKV_N / 128, ROWS / 128), 128, GEMM_SMEM_BYTES>>>(
        xh, wqkvt, bqkv, qkv, D_MODEL, QKV_N, 2);

    transpose_h_kernel<<<dim3(D_MODEL / 32, D_MODEL / 32), 256>>>(wo, wot, D_MODEL, D_MODEL);
    transpose_h_kernel<<<dim3(D_FF / 32,    D_MODEL / 32), 256>>>(w1, w1t, D_MODEL, D_FF);
    transpose_h_kernel<<<dim3(D_MODEL / 32, D_FF / 32),    256>>>(w2, w2t, D_FF, D_MODEL);

    attn_f16<<<dim3(S_ / 64, NUM_HEADS, B_), 128>>>(qkv, mask, ap);

    gemm_f16<<<dim3(D_MODEL / 128, ROWS / 128), 128, GEMM_SMEM_BYTES>>>(
        ap, wot, bo, pp, D_MODEL, D_MODEL, 0);
    add_ln_kernel<<<ROWS, 256>>>(x, pp, ln1g, ln1b, x1p, x1h);

    gemm_f16<<<dim3(D_FF / 128, ROWS / 128), 128, GEMM_SMEM_BYTES>>>(
        x1h, w1t, b1, f1p, D_MODEL, D_FF, 1);
    gemm_f16<<<dim3(D_MODEL / 128, ROWS / 128), 128, GEMM_SMEM_BYTES>>>(
        f1p, w2t, b2, f2p, D_FF, D_MODEL, 0);
    add_ln_kernel<<<ROWS, 256>>>(x1p, f2p, ln2g, ln2b, (float*)d_out, (__half*)0);
}